// round 12
// baseline (speedup 1.0000x reference)
#include <cuda_runtime.h>
#include <cuda_bf16.h>
#include <math.h>
#include <stdint.h>

// ---------------------------------------------------------------------------
// Problem constants
// ---------------------------------------------------------------------------
#define BATCH   16
#define DIM     192
#define HW      56
#define PIX     3136            // 56*56
#define NPIX    50176           // 16*3136
#define WS      7
#define SHIFTV  3
#define NWIN    49
#define HEADS   6
#define HD      32
#define NW_GRID 8
#define SCALE_Q 0.1767766952966369f

typedef __nv_bfloat16 bf16;

// ---------------------------------------------------------------------------
// Scratch buffers (allocation-free: device globals)
// ---------------------------------------------------------------------------
__device__ __align__(128) bf16  gb_a   [NPIX * DIM];   // win (ln1 out) / h2 (ln2 out)
__device__ __align__(128) bf16  gb_b   [NPIX * DIM];   // attn out
__device__ __align__(128) bf16  gb_big [NPIX * 768];   // qkv out (576 used) / fc1 out
__device__ __align__(128) bf16  gb_po  [NPIX * DIM];   // proj out (bf16)
__device__ __align__(128) float g_x1   [NPIX * DIM];   // residual-1 (NCHW)
// transposed bf16 weights Wt[N][K]
__device__ __align__(128) bf16 g_qkv_wt [576 * 192];
__device__ __align__(128) bf16 g_proj_wt[192 * 192];
__device__ __align__(128) bf16 g_fc1_wt [768 * 192];
__device__ __align__(128) bf16 g_fc2_wt [192 * 768];
// precomputed attention bias+mask matrices: [head*4+cls][64][64] bf16
__device__ __align__(128) bf16 g_biasmat[24 * 64 * 64];

// ---------------------------------------------------------------------------
// PTX helpers
// ---------------------------------------------------------------------------
__device__ __forceinline__ void mma_bf16(float c[4], const uint32_t a[4],
                                         const uint32_t b0, const uint32_t b1) {
    asm volatile(
        "mma.sync.aligned.m16n8k16.row.col.f32.bf16.bf16.f32 "
        "{%0,%1,%2,%3}, {%4,%5,%6,%7}, {%8,%9}, {%0,%1,%2,%3};"
        : "+f"(c[0]), "+f"(c[1]), "+f"(c[2]), "+f"(c[3])
        : "r"(a[0]), "r"(a[1]), "r"(a[2]), "r"(a[3]),
          "r"(b0), "r"(b1));
}
__device__ __forceinline__ void ldsm4(uint32_t r[4], uint32_t addr) {
    asm volatile("ldmatrix.sync.aligned.m8n8.x4.shared.b16 {%0,%1,%2,%3}, [%4];"
                 : "=r"(r[0]), "=r"(r[1]), "=r"(r[2]), "=r"(r[3]) : "r"(addr));
}
__device__ __forceinline__ void ldsm4t(uint32_t r[4], uint32_t addr) {
    asm volatile("ldmatrix.sync.aligned.m8n8.x4.trans.shared.b16 {%0,%1,%2,%3}, [%4];"
                 : "=r"(r[0]), "=r"(r[1]), "=r"(r[2]), "=r"(r[3]) : "r"(addr));
}
__device__ __forceinline__ void cp16(uint32_t dst, const void* src) {
    asm volatile("cp.async.cg.shared.global [%0], [%1], 16;"
                 :: "r"(dst), "l"(src));
}
__device__ __forceinline__ void cp_commit() {
    asm volatile("cp.async.commit_group;" ::: "memory");
}
template <int N>
__device__ __forceinline__ void cp_wait() {
    asm volatile("cp.async.wait_group %0;" :: "n"(N) : "memory");
}
__device__ __forceinline__ uint32_t sptr(const void* p) {
    return (uint32_t)__cvta_generic_to_shared(p);
}
__device__ __forceinline__ float bflo(uint32_t u) {
    return __uint_as_float(u << 16);
}
__device__ __forceinline__ float bfhi(uint32_t u) {
    return __uint_as_float(u & 0xffff0000u);
}
__device__ __forceinline__ uint32_t packbf(float a, float b) {
    __nv_bfloat162 t = __floats2bfloat162_rn(a, b);
    return *(uint32_t*)&t;
}

// ---------------------------------------------------------------------------
// Persistent bf16 tensor-core GEMM: C[NPIX,Ntot] = A[NPIX,K] @ Wt[N,K]^T + bias
// BM=256, BN=96, BKC=32; 256 threads = 8 warps (4M x 2N), warp tile 64x48.
// 1 CTA/SM persistent; balanced tile split; m-fastest tile order.
// BRES=1 (K=192): full B tile resident in smem (6 panels); loop stages only A.
// BRES=0 (fc2):   A and B staged per k-stage (3-buf rings).
// MODE: 1 = bf16+GELU out, 2 = bf16 out,
//       3 = fp32 NCHW out with fused residual add (out = x1 + acc+bias).
// ---------------------------------------------------------------------------
#define BM 256
#define BN 96
#define BKC 32
#define MT (NPIX / BM)          // 196 m-tiles
#define ASTG (BM * 64)          // 16384 per A stage
#define BPNL (BN * 64)          // 6144 per B panel
#define SMEM_BRES1 (3 * ASTG + 6 * BPNL)   // 86016
#define SMEM_BRES0 (3 * ASTG + 3 * BPNL)   // 67584

template <int MODE, int BRES>
__global__ __launch_bounds__(256, 1)
void mma_gemm(const bf16* __restrict__ A, const bf16* __restrict__ Bt,
              const float* __restrict__ bias, void* __restrict__ Cout,
              const float* __restrict__ x1aux, int Ntot, int K) {
    extern __shared__ char dsm[];
    const uint32_t aAbase = sptr(dsm);
    const uint32_t aBbase = aAbase + 3 * ASTG;

    int tid = threadIdx.x, lane = tid & 31, wid = tid >> 5;
    int wm = wid & 3, wn = wid >> 2;

    const int S = K / BKC;
    int NT = Ntot / BN;
    int ntiles = MT * NT;
    int base = ntiles / gridDim.x, rem = ntiles % gridDim.x;
    int bidx = blockIdx.x;
    int t0 = bidx * base + (bidx < rem ? bidx : rem);
    int t1 = t0 + base + (bidx < rem ? 1 : 0);
    if (t0 >= t1) return;

    // ldmatrix per-lane address components (validated pattern)
    uint32_t aRow[4], aSw[4];
    int aHalf = lane >> 4;
#pragma unroll
    for (int tm = 0; tm < 4; ++tm) {
        int r = wm * 64 + tm * 16 + (lane & 15);
        aRow[tm] = r * 64;
        aSw[tm]  = (r >> 1) & 3;
    }
    uint32_t bRow[3], bSw[3];
    int bHalf = (lane >> 3) & 1;
#pragma unroll
    for (int p = 0; p < 3; ++p) {
        int r = wn * 48 + p * 16 + ((lane >> 4) << 3) + (lane & 7);
        bRow[p] = r * 64;
        bSw[p]  = (r >> 1) & 3;
    }

    float acc[4][6][4];
#pragma unroll
    for (int i = 0; i < 4; ++i)
#pragma unroll
        for (int j = 0; j < 6; ++j)
#pragma unroll
            for (int l = 0; l < 4; ++l) acc[i][j][l] = 0.f;

    auto compute = [&](uint32_t bA, uint32_t bB) {
#pragma unroll
        for (int kss = 0; kss < 2; ++kss) {
            uint32_t af[4][4], bq[3][4];
#pragma unroll
            for (int tm = 0; tm < 4; ++tm)
                ldsm4(af[tm], bA + aRow[tm]
                      + ((((kss << 1) | aHalf) ^ aSw[tm]) << 4));
#pragma unroll
            for (int p = 0; p < 3; ++p)
                ldsm4(bq[p], bB + bRow[p]
                      + ((((kss << 1) | bHalf) ^ bSw[p]) << 4));
#pragma unroll
            for (int tm = 0; tm < 4; ++tm)
#pragma unroll
                for (int tn = 0; tn < 6; ++tn)
                    mma_bf16(acc[tm][tn], af[tm],
                             bq[tn >> 1][(tn & 1) << 1],
                             bq[tn >> 1][((tn & 1) << 1) + 1]);
        }
    };

    auto epi = [&](int m0, int n0) {
        int q = lane & 3;
#pragma unroll
        for (int tm = 0; tm < 4; ++tm) {
            int r = m0 + wm * 64 + tm * 16 + (lane >> 2);
            size_t base1 = 0, base2 = 0;
            if (MODE == 3) {
                int b1 = r / PIX, yx1 = r % PIX;
                int r2 = r + 8;
                int b2 = r2 / PIX, yx2 = r2 % PIX;
                base1 = (size_t)b1 * (DIM * PIX) + yx1;
                base2 = (size_t)b2 * (DIM * PIX) + yx2;
            }
#pragma unroll
            for (int tn = 0; tn < 6; ++tn) {
                int cl = wn * 48 + tn * 8 + (q << 1);
                float b0 = __ldg(bias + n0 + cl);
                float b1v = __ldg(bias + n0 + cl + 1);
                float v0 = acc[tm][tn][0] + b0;
                float v1 = acc[tm][tn][1] + b1v;
                float v2 = acc[tm][tn][2] + b0;
                float v3 = acc[tm][tn][3] + b1v;
                if (MODE == 1) {
                    v0 = 0.5f * v0 * (1.f + erff(v0 * 0.70710678118654752f));
                    v1 = 0.5f * v1 * (1.f + erff(v1 * 0.70710678118654752f));
                    v2 = 0.5f * v2 * (1.f + erff(v2 * 0.70710678118654752f));
                    v3 = 0.5f * v3 * (1.f + erff(v3 * 0.70710678118654752f));
                }
                if (MODE == 3) {
                    float* O = (float*)Cout;
                    size_t o00 = base1 + (size_t)(n0 + cl) * PIX;
                    size_t o01 = base1 + (size_t)(n0 + cl + 1) * PIX;
                    size_t o10 = base2 + (size_t)(n0 + cl) * PIX;
                    size_t o11 = base2 + (size_t)(n0 + cl + 1) * PIX;
                    O[o00] = x1aux[o00] + v0;
                    O[o01] = x1aux[o01] + v1;
                    O[o10] = x1aux[o10] + v2;
                    O[o11] = x1aux[o11] + v3;
                } else {
                    bf16* C = (bf16*)Cout;
                    *(__nv_bfloat162*)(C + (size_t)r * Ntot + n0 + cl) =
                        __floats2bfloat162_rn(v0, v1);
                    *(__nv_bfloat162*)(C + (size_t)(r + 8) * Ntot + n0 + cl) =
                        __floats2bfloat162_rn(v2, v3);
                }
            }
        }
#pragma unroll
        for (int i = 0; i < 4; ++i)
#pragma unroll
            for (int j = 0; j < 6; ++j)
#pragma unroll
                for (int l = 0; l < 4; ++l) acc[i][j][l] = 0.f;
    };

    if (BRES) {
        // ---- B resident: process tiles grouped by n-index ----
        int t = t0;
        while (t < t1) {
            int nIdx = t / MT;
            int tend = (nIdx + 1) * MT; if (tend > t1) tend = t1;
            int n0 = nIdx * BN;
            __syncthreads();               // drain previous group's smem use
            {   // load all S B panels (S*384 16B-groups)
                int total = S * 384;
                for (int e = tid; e < total; e += 256) {
                    int panel = e / 384;
                    int rg = e - panel * 384;
                    int r = rg >> 2, g4 = rg & 3;
                    uint32_t dst = aBbase + panel * BPNL + r * 64
                                 + ((g4 ^ ((r >> 1) & 3)) << 4);
                    cp16(dst, Bt + (size_t)(n0 + r) * K + panel * BKC + g4 * 8);
                }
                cp_commit();
            }
            int G = (tend - t) * S;
            int sm0 = (t % MT) * BM, sks = 0, sbuf = 0;
            auto stageA = [&]() {
                uint32_t dstb = aAbase + sbuf * ASTG;
                int kc = sks * BKC;
#pragma unroll
                for (int i = 0; i < 4; ++i) {
                    int e = (i << 8) + tid;
                    int row = e >> 2, g4 = e & 3;
                    cp16(dstb + row * 64 + ((g4 ^ ((row >> 1) & 3)) << 4),
                         A + (size_t)(sm0 + row) * K + kc + g4 * 8);
                }
                cp_commit();
                if (++sks == S) { sks = 0; sm0 += BM; }
                if (++sbuf == 3) sbuf = 0;
            };
            stageA(); stageA();            // prologue: 2 stages in flight
            int cm0 = (t % MT) * BM, cks = 0, cbuf = 0;
            for (int g = 0; g < G; ++g) {
                if (g + 1 < G) cp_wait<1>(); else cp_wait<0>();
                __syncthreads();
                if (g + 2 < G) stageA();
                compute(aAbase + cbuf * ASTG, aBbase + cks * BPNL);
                if (++cks == S) { cks = 0; epi(cm0, n0); cm0 += BM; }
                if (++cbuf == 3) cbuf = 0;
            }
            t = tend;
        }
    } else {
        // ---- streaming B (fc2): one continuous pipeline over the chunk ----
        int G = (t1 - t0) * S;
        int sm0 = (t0 % MT) * BM, sn0 = (t0 / MT) * BN, sks = 0, sbuf = 0;
        auto stageAB = [&]() {
            uint32_t dA = aAbase + sbuf * ASTG;
            uint32_t dB = aBbase + sbuf * BPNL;
            int kc = sks * BKC;
#pragma unroll
            for (int i = 0; i < 4; ++i) {
                int e = (i << 8) + tid;
                int row = e >> 2, g4 = e & 3;
                cp16(dA + row * 64 + ((g4 ^ ((row >> 1) & 3)) << 4),
                     A + (size_t)(sm0 + row) * K + kc + g4 * 8);
            }
            {
                int row = tid >> 2, g4 = tid & 3;
                cp16(dB + row * 64 + ((g4 ^ ((row >> 1) & 3)) << 4),
                     Bt + (size_t)(sn0 + row) * K + kc + g4 * 8);
            }
            if (tid < 128) {
                int e = 256 + tid;
                int row = e >> 2, g4 = e & 3;
                cp16(dB + row * 64 + ((g4 ^ ((row >> 1) & 3)) << 4),
                     Bt + (size_t)(sn0 + row) * K + kc + g4 * 8);
            }
            cp_commit();
            if (++sks == S) {
                sks = 0; sm0 += BM;
                if (sm0 == NPIX) { sm0 = 0; sn0 += BN; }
            }
            if (++sbuf == 3) sbuf = 0;
        };
        stageAB(); stageAB();
        int cm0 = (t0 % MT) * BM, cn0 = (t0 / MT) * BN, cks = 0, cbuf = 0;
        for (int g = 0; g < G; ++g) {
            if (g + 1 < G) cp_wait<1>(); else cp_wait<0>();
            __syncthreads();
            if (g + 2 < G) stageAB();
            compute(aAbase + cbuf * ASTG, aBbase + cbuf * BPNL);
            if (++cks == S) {
                cks = 0; epi(cm0, cn0); cm0 += BM;
                if (cm0 == NPIX) { cm0 = 0; cn0 += BN; }
            }
            if (++cbuf == 3) cbuf = 0;
        }
    }
}

// ---------------------------------------------------------------------------
// Bias matrices: [h*4+cls][q(64)][k(64)] = rel_bias + shift-mask, padded = -1e9
// ---------------------------------------------------------------------------
__global__ void bias_build(const float* __restrict__ rel_bias,
                           bf16* __restrict__ bm) {
    int mat = blockIdx.x;            // 0..23
    int h = mat >> 2, cls = mat & 3;
    for (int e = threadIdx.x; e < 4096; e += 256) {
        int qq = e >> 6, kk = e & 63;
        float v = -1e9f;
        if (qq < NWIN && kk < NWIN) {
            int qi = qq / WS, qj = qq % WS, ki = kk / WS, kj = kk % WS;
            int ryq = (cls & 2) ? ((qi < WS - SHIFTV) ? 1 : 2) : 0;
            int rxq = (cls & 1) ? ((qj < WS - SHIFTV) ? 1 : 2) : 0;
            int ryk = (cls & 2) ? ((ki < WS - SHIFTV) ? 1 : 2) : 0;
            int rxk = (cls & 1) ? ((kj < WS - SHIFTV) ? 1 : 2) : 0;
            if (ryq == ryk && rxq == rxk)
                v = rel_bias[((qi - ki + 6) * 13 + (qj - kj + 6)) * HEADS + h];
        }
        bm[mat * 4096 + e] = __float2bfloat16(v);
    }
}

// ---------------------------------------------------------------------------
// K3: MMA windowed attention (unchanged — passing)
// ---------------------------------------------------------------------------
__global__ __launch_bounds__(128)
void attn_mma_kernel(const bf16* __restrict__ qkv,
                     const bf16* __restrict__ biasmat,
                     bf16* __restrict__ ao) {
    __shared__ __align__(16) bf16 sm[3 * 64 * 32];   // Q,K,V: 64 rows x 64B each

    int blk = blockIdx.x;
    int h = blk % HEADS, w = blk / HEADS;
    int widx = w & 63;
    int wi = widx >> 3, wj = widx & 7;
    int cls = ((wi == 7) ? 2 : 0) + ((wj == 7) ? 1 : 0);
    const bf16* bm = biasmat + (size_t)(h * 4 + cls) * 4096;
    int r0 = w * NWIN;
    int tid = threadIdx.x, lane = tid & 31, wid = tid >> 5;

    uint32_t sb = sptr(sm);

    const uint4 z4 = make_uint4(0, 0, 0, 0);
    for (int e = tid; e < 768; e += 128) {
        int mat = e >> 8;               // 0=Q 1=K 2=V
        int rg  = e & 255;
        int row = rg >> 2, g = rg & 3;
        uint32_t dst = sb + mat * 4096 + row * 64 + ((g ^ ((row >> 1) & 3)) << 4);
        uint4 v = z4;
        if (row < NWIN)
            v = *(const uint4*)(qkv + (size_t)(r0 + row) * 576 + mat * 192
                                + h * HD + g * 8);
        *(uint4*)((char*)sm + (dst - sb)) = v;
    }
    __syncthreads();

    int qbase = wid * 16;
    int rw = lane & 7;

    float sacc[8][4];
#pragma unroll
    for (int n = 0; n < 8; ++n)
#pragma unroll
        for (int l = 0; l < 4; ++l) sacc[n][l] = 0.f;

    int aHalf = lane >> 4;
    int arow = qbase + (lane & 15);
    uint32_t aAddrBase = sb + arow * 64;
    uint32_t aSw = (arow >> 1) & 3;
    int bHalf = (lane >> 3) & 1;

#pragma unroll
    for (int c = 0; c < 2; ++c) {
        uint32_t af[4];
        ldsm4(af, aAddrBase + ((((c << 1) | aHalf) ^ aSw) << 4));
#pragma unroll
        for (int t = 0; t < 4; ++t) {
            int brow = t * 16 + ((lane >> 4) << 3) + rw;
            uint32_t bq[4];
            ldsm4(bq, sb + 4096 + brow * 64
                  + ((((c << 1) | bHalf) ^ ((brow >> 1) & 3)) << 4));
            mma_bf16(sacc[2 * t],     af, bq[0], bq[1]);
            mma_bf16(sacc[2 * t + 1], af, bq[2], bq[3]);
        }
    }

    int rA = qbase + (lane >> 2);
    int rB = rA + 8;
    const bf16* bmA = bm + rA * 64 + ((lane & 3) << 1);
    const bf16* bmB = bm + rB * 64 + ((lane & 3) << 1);

    float mx0 = -1e30f, mx1 = -1e30f;
#pragma unroll
    for (int n = 0; n < 8; ++n) {
        uint32_t bb0 = *(const uint32_t*)(bmA + n * 8);
        uint32_t bb1 = *(const uint32_t*)(bmB + n * 8);
        sacc[n][0] = sacc[n][0] * SCALE_Q + bflo(bb0);
        sacc[n][1] = sacc[n][1] * SCALE_Q + bfhi(bb0);
        sacc[n][2] = sacc[n][2] * SCALE_Q + bflo(bb1);
        sacc[n][3] = sacc[n][3] * SCALE_Q + bfhi(bb1);
        mx0 = fmaxf(mx0, fmaxf(sacc[n][0], sacc[n][1]));
        mx1 = fmaxf(mx1, fmaxf(sacc[n][2], sacc[n][3]));
    }
    mx0 = fmaxf(mx0, __shfl_xor_sync(0xffffffffu, mx0, 1));
    mx0 = fmaxf(mx0, __shfl_xor_sync(0xffffffffu, mx0, 2));
    mx1 = fmaxf(mx1, __shfl_xor_sync(0xffffffffu, mx1, 1));
    mx1 = fmaxf(mx1, __shfl_xor_sync(0xffffffffu, mx1, 2));

    float sum0 = 0.f, sum1 = 0.f;
#pragma unroll
    for (int n = 0; n < 8; ++n) {
        sacc[n][0] = __expf(sacc[n][0] - mx0);
        sacc[n][1] = __expf(sacc[n][1] - mx0);
        sacc[n][2] = __expf(sacc[n][2] - mx1);
        sacc[n][3] = __expf(sacc[n][3] - mx1);
        sum0 += sacc[n][0] + sacc[n][1];
        sum1 += sacc[n][2] + sacc[n][3];
    }
    sum0 += __shfl_xor_sync(0xffffffffu, sum0, 1);
    sum0 += __shfl_xor_sync(0xffffffffu, sum0, 2);
    sum1 += __shfl_xor_sync(0xffffffffu, sum1, 1);
    sum1 += __shfl_xor_sync(0xffffffffu, sum1, 2);
    float inv0 = 1.f / sum0, inv1 = 1.f / sum1;

    uint32_t pA[8], pB[8];
#pragma unroll
    for (int n = 0; n < 8; ++n) {
        pA[n] = packbf(sacc[n][0] * inv0, sacc[n][1] * inv0);
        pB[n] = packbf(sacc[n][2] * inv1, sacc[n][3] * inv1);
    }

    float oacc[4][4];
#pragma unroll
    for (int d = 0; d < 4; ++d)
#pragma unroll
        for (int l = 0; l < 4; ++l) oacc[d][l] = 0.f;

#pragma unroll
    for (int kc = 0; kc < 4; ++kc) {
        uint32_t af[4] = { pA[2 * kc], pB[2 * kc], pA[2 * kc + 1], pB[2 * kc + 1] };
        int vrow = kc * 16 + (((lane >> 3) & 1) << 3) + rw;
        uint32_t vswz = (vrow >> 1) & 3;
        int ghalf = (lane >> 4) & 1;
        uint32_t v01[4], v23[4];
        ldsm4t(v01, sb + 8192 + vrow * 64 + (((0 + ghalf) ^ vswz) << 4));
        ldsm4t(v23, sb + 8192 + vrow * 64 + (((2 + ghalf) ^ vswz) << 4));
        mma_bf16(oacc[0], af, v01[0], v01[1]);
        mma_bf16(oacc[1], af, v01[2], v01[3]);
        mma_bf16(oacc[2], af, v23[0], v23[1]);
        mma_bf16(oacc[3], af, v23[2], v23[3]);
    }

    int colb = h * HD + ((lane & 3) << 1);
    if (rA < NWIN) {
        bf16* op = ao + (size_t)(r0 + rA) * DIM + colb;
#pragma unroll
        for (int d = 0; d < 4; ++d)
            *(uint32_t*)(op + d * 8) = packbf(oacc[d][0], oacc[d][1]);
    }
    if (rB < NWIN) {
        bf16* op = ao + (size_t)(r0 + rB) * DIM + colb;
#pragma unroll
        for (int d = 0; d < 4; ++d)
            *(uint32_t*)(op + d * 8) = packbf(oacc[d][2], oacc[d][3]);
    }
}

// ---------------------------------------------------------------------------
// All 4 weight transposes (+bf16 convert) in ONE launch
// ---------------------------------------------------------------------------
__global__ void transpose_all(const float* __restrict__ w0, const float* __restrict__ w1,
                              const float* __restrict__ w2, const float* __restrict__ w3,
                              bf16* __restrict__ t0, bf16* __restrict__ t1,
                              bf16* __restrict__ t2, bf16* __restrict__ t3) {
    __shared__ float t[32][33];
    int bid = blockIdx.x;
    const float* W; bf16* Wt; int K, N, tn, tk;
    if (bid < 108)      { W = w0; Wt = t0; K = 192; N = 576; tn = bid % 18; tk = bid / 18; }
    else if (bid < 144) { bid -= 108; W = w1; Wt = t1; K = 192; N = 192; tn = bid % 6;  tk = bid / 6; }
    else if (bid < 288) { bid -= 144; W = w2; Wt = t2; K = 192; N = 768; tn = bid % 24; tk = bid / 24; }
    else                { bid -= 288; W = w3; Wt = t3; K = 768; N = 192; tn = bid % 6;  tk = bid / 6; }
    int k0 = tk * 32, n0 = tn * 32;
    int tx = threadIdx.x, ty = threadIdx.y;
#pragma unroll
    for (int i = 0; i < 32; i += 8)
        t[ty + i][tx] = W[(size_t)(k0 + ty + i) * N + n0 + tx];
    __syncthreads();
#pragma unroll
    for (int i = 0; i < 32; i += 8)
        Wt[(size_t)(n0 + ty + i) * K + k0 + tx] = __float2bfloat16(t[tx][ty + i]);
}

// ---------------------------------------------------------------------------
// K1: LayerNorm1 + roll(-3,-3) + window partition -> bf16 win
// ---------------------------------------------------------------------------
__global__ __launch_bounds__(256)
void ln1_win_kernel(const float* __restrict__ x,
                    const float* __restrict__ gam,
                    const float* __restrict__ bet,
                    bf16* __restrict__ win) {
    __shared__ float sm[32][193];
    int p0  = blockIdx.x * 32;
    int b   = p0 / PIX, yx0 = p0 % PIX;
    int tid = threadIdx.x, warp = tid >> 5, lane = tid & 31;

    const float* xb = x + (size_t)b * (DIM * PIX) + yx0;
#pragma unroll
    for (int cc = 0; cc < 24; ++cc) {
        int c = warp + cc * 8;
        sm[lane][c] = xb[(size_t)c * PIX + lane];
    }
    __syncthreads();

#pragma unroll
    for (int t = 0; t < 4; ++t) {
        int pix = warp * 4 + t;
        float v[6], s = 0.f, sq = 0.f;
#pragma unroll
        for (int j = 0; j < 6; ++j) {
            float u = sm[pix][lane + j * 32];
            v[j] = u; s += u; sq += u * u;
        }
#pragma unroll
        for (int o = 16; o; o >>= 1) {
            s  += __shfl_xor_sync(0xffffffffu, s,  o);
            sq += __shfl_xor_sync(0xffffffffu, sq, o);
        }
        float mu   = s * (1.f / DIM);
        float var  = sq * (1.f / DIM) - mu * mu;
        float rstd = rsqrtf(var + 1e-5f);

        int yx = yx0 + pix;
        int y  = yx / HW, xx = yx % HW;
        int y2 = (y  + HW - SHIFTV) % HW;
        int x2 = (xx + HW - SHIFTV) % HW;
        int r  = b * PIX + ((y2 / WS) * NW_GRID + (x2 / WS)) * NWIN
               + (y2 % WS) * WS + (x2 % WS);
        bf16* wp = win + (size_t)r * DIM;
#pragma unroll
        for (int j = 0; j < 6; ++j) {
            int c = lane + j * 32;
            wp[c] = __float2bfloat16((v[j] - mu) * rstd * gam[c] + bet[c]);
        }
    }
}

// ---------------------------------------------------------------------------
// K5: x1 = x + window-reverse(proj_out bf16);  h2 = LN2(x1) -> bf16
// ---------------------------------------------------------------------------
__global__ __launch_bounds__(256)
void addln2_kernel(const float* __restrict__ x,
                   const bf16* __restrict__ po,
                   const float* __restrict__ gam,
                   const float* __restrict__ bet,
                   float* __restrict__ x1,
                   bf16* __restrict__ h2) {
    __shared__ float sm[32][193];
    int p0  = blockIdx.x * 32;
    int b   = p0 / PIX, yx0 = p0 % PIX;
    int tid = threadIdx.x, warp = tid >> 5, lane = tid & 31;

#pragma unroll
    for (int t = 0; t < 4; ++t) {
        int pix = warp * 4 + t;
        int yx = yx0 + pix;
        int y  = yx / HW, xx = yx % HW;
        int y2 = (y  + HW - SHIFTV) % HW;
        int x2 = (xx + HW - SHIFTV) % HW;
        int r  = b * PIX + ((y2 / WS) * NW_GRID + (x2 / WS)) * NWIN
               + (y2 % WS) * WS + (x2 % WS);
        const bf16* pp = po + (size_t)r * DIM;
#pragma unroll
        for (int j = 0; j < 6; ++j) {
            int c = lane + j * 32;
            sm[pix][c] = __bfloat162float(pp[c]);
        }
    }
    __syncthreads();

    const float* xb = x  + (size_t)b * (DIM * PIX) + yx0;
    float*       xo = x1 + (size_t)b * (DIM * PIX) + yx0;
#pragma unroll
    for (int cc = 0; cc < 24; ++cc) {
        int c = warp + cc * 8;
        float v = xb[(size_t)c * PIX + lane] + sm[lane][c];
        xo[(size_t)c * PIX + lane] = v;
        sm[lane][c] = v;
    }
    __syncthreads();

#pragma unroll
    for (int t = 0; t < 4; ++t) {
        int pix = warp * 4 + t;
        float v[6], s = 0.f, sq = 0.f;
#pragma unroll
        for (int j = 0; j < 6; ++j) {
            float u = sm[pix][lane + j * 32];
            v[j] = u; s += u; sq += u * u;
        }
#pragma unroll
        for (int o = 16; o; o >>= 1) {
            s  += __shfl_xor_sync(0xffffffffu, s,  o);
            sq += __shfl_xor_sync(0xffffffffu, sq, o);
        }
        float mu   = s * (1.f / DIM);
        float var  = sq * (1.f / DIM) - mu * mu;
        float rstd = rsqrtf(var + 1e-5f);

        bf16* hp = h2 + (size_t)(p0 + pix) * DIM;
#pragma unroll
        for (int j = 0; j < 6; ++j) {
            int c = lane + j * 32;
            hp[c] = __float2bfloat16((v[j] - mu) * rstd * gam[c] + bet[c]);
        }
    }
}

// ---------------------------------------------------------------------------
// Launch
// ---------------------------------------------------------------------------
extern "C" void kernel_launch(void* const* d_in, const int* in_sizes, int n_in,
                              void* d_out, int out_size) {
    const float* x      = (const float*)d_in[0];
    const float* n1g    = (const float*)d_in[1];
    const float* n1b    = (const float*)d_in[2];
    const float* qkv_w  = (const float*)d_in[3];
    const float* qkv_b  = (const float*)d_in[4];
    const float* proj_w = (const float*)d_in[5];
    const float* proj_b = (const float*)d_in[6];
    const float* relb   = (const float*)d_in[7];
    const float* n2g    = (const float*)d_in[8];
    const float* n2b    = (const float*)d_in[9];
    const float* fc1_w  = (const float*)d_in[10];
    const float* fc1_b  = (const float*)d_in[11];
    const float* fc2_w  = (const float*)d_in[12];
    const float* fc2_b  = (const float*)d_in[13];
    float* out = (float*)d_out;

    bf16 *ba, *bb, *bg, *bpo, *wqkv, *wproj, *wfc1, *wfc2, *bmat;
    float *bx1;
    cudaGetSymbolAddress((void**)&ba,   gb_a);
    cudaGetSymbolAddress((void**)&bb,   gb_b);
    cudaGetSymbolAddress((void**)&bg,   gb_big);
    cudaGetSymbolAddress((void**)&bpo,  gb_po);
    cudaGetSymbolAddress((void**)&bx1,  g_x1);
    cudaGetSymbolAddress((void**)&wqkv, g_qkv_wt);
    cudaGetSymbolAddress((void**)&wproj,g_proj_wt);
    cudaGetSymbolAddress((void**)&wfc1, g_fc1_wt);
    cudaGetSymbolAddress((void**)&wfc2, g_fc2_wt);
    cudaGetSymbolAddress((void**)&bmat, g_biasmat);

    cudaFuncSetAttribute(mma_gemm<2,1>, cudaFuncAttributeMaxDynamicSharedMemorySize, SMEM_BRES1);
    cudaFuncSetAttribute(mma_gemm<1,1>, cudaFuncAttributeMaxDynamicSharedMemorySize, SMEM_BRES1);
    cudaFuncSetAttribute(mma_gemm<3,0>, cudaFuncAttributeMaxDynamicSharedMemorySize, SMEM_BRES0);

    int dev = 0, nsm = 148;
    cudaGetDevice(&dev);
    cudaDeviceGetAttribute(&nsm, cudaDevAttrMultiProcessorCount, dev);
    int grid = nsm;

    // 0) weight transposes + bias/mask matrices
    transpose_all<<<432, dim3(32, 8)>>>(qkv_w, proj_w, fc1_w, fc2_w,
                                        wqkv, wproj, wfc1, wfc2);
    bias_build<<<24, 256>>>(relb, bmat);

    // 1) LN1 + roll + window partition -> ba = win[50176,192] bf16
    ln1_win_kernel<<<NPIX / 32, 256>>>(x, n1g, n1b, ba);

    // 2) QKV GEMM -> bg[50176,576] bf16
    mma_gemm<2,1><<<grid, 256, SMEM_BRES1>>>(ba, wqkv, qkv_b, bg,
                                             nullptr, 576, 192);
    // 3) MMA attention -> bb[50176,192] bf16
    attn_mma_kernel<<<1024 * HEADS, 128>>>(bg, bmat, bb);

    // 4) proj GEMM -> bpo bf16
    mma_gemm<2,1><<<grid, 256, SMEM_BRES1>>>(bb, wproj, proj_b, bpo,
                                             nullptr, 192, 192);
    // 5) residual + LN2 -> bx1 (NCHW fp32), ba = h2 bf16
    addln2_kernel<<<NPIX / 32, 256>>>(x, bpo, n2g, n2b, bx1, ba);

    // 6) fc1 + GELU -> bg[50176,768] bf16
    mma_gemm<1,1><<<grid, 256, SMEM_BRES1>>>(ba, wfc1, fc1_b, bg,
                                             nullptr, 768, 192);
    // 7) fc2 + fused residual -> out (NCHW fp32)
    mma_gemm<3,0><<<grid, 256, SMEM_BRES0>>>(bg, wfc2, fc2_b, out,
                                             bx1, 192, 768);
}

// round 13
// speedup vs baseline: 1.1276x; 1.1276x over previous
#include <cuda_runtime.h>
#include <cuda_bf16.h>
#include <math.h>
#include <stdint.h>

// ---------------------------------------------------------------------------
// Problem constants
// ---------------------------------------------------------------------------
#define BATCH   16
#define DIM     192
#define HW      56
#define PIX     3136            // 56*56
#define NPIX    50176           // 16*3136
#define WS      7
#define SHIFTV  3
#define NWIN    49
#define HEADS   6
#define HD      32
#define NW_GRID 8
#define SCALE_Q 0.1767766952966369f

typedef __nv_bfloat16 bf16;

// ---------------------------------------------------------------------------
// Scratch buffers (allocation-free: device globals)
// ---------------------------------------------------------------------------
__device__ __align__(128) bf16  gb_a   [NPIX * DIM];   // win (ln1 out) / h2 (ln2 out)
__device__ __align__(128) bf16  gb_b   [NPIX * DIM];   // attn out
__device__ __align__(128) bf16  gb_big [NPIX * 768];   // qkv out (576 used) / fc1 out
__device__ __align__(128) bf16  gb_po  [NPIX * DIM];   // proj out (bf16)
__device__ __align__(128) float g_x1   [NPIX * DIM];   // residual-1 (NCHW)
// transposed bf16 weights Wt[N][K]
__device__ __align__(128) bf16 g_qkv_wt [576 * 192];
__device__ __align__(128) bf16 g_proj_wt[192 * 192];
__device__ __align__(128) bf16 g_fc1_wt [768 * 192];
__device__ __align__(128) bf16 g_fc2_wt [192 * 768];
// precomputed attention bias+mask matrices: [head*4+cls][64][64] bf16
__device__ __align__(128) bf16 g_biasmat[24 * 64 * 64];

// ---------------------------------------------------------------------------
// PTX helpers
// ---------------------------------------------------------------------------
__device__ __forceinline__ void mma_bf16(float c[4], const uint32_t a[4],
                                         const uint32_t b0, const uint32_t b1) {
    asm volatile(
        "mma.sync.aligned.m16n8k16.row.col.f32.bf16.bf16.f32 "
        "{%0,%1,%2,%3}, {%4,%5,%6,%7}, {%8,%9}, {%0,%1,%2,%3};"
        : "+f"(c[0]), "+f"(c[1]), "+f"(c[2]), "+f"(c[3])
        : "r"(a[0]), "r"(a[1]), "r"(a[2]), "r"(a[3]),
          "r"(b0), "r"(b1));
}
__device__ __forceinline__ void ldsm4(uint32_t r[4], uint32_t addr) {
    asm volatile("ldmatrix.sync.aligned.m8n8.x4.shared.b16 {%0,%1,%2,%3}, [%4];"
                 : "=r"(r[0]), "=r"(r[1]), "=r"(r[2]), "=r"(r[3]) : "r"(addr));
}
__device__ __forceinline__ void ldsm4t(uint32_t r[4], uint32_t addr) {
    asm volatile("ldmatrix.sync.aligned.m8n8.x4.trans.shared.b16 {%0,%1,%2,%3}, [%4];"
                 : "=r"(r[0]), "=r"(r[1]), "=r"(r[2]), "=r"(r[3]) : "r"(addr));
}
__device__ __forceinline__ void cp16(uint32_t dst, const void* src) {
    asm volatile("cp.async.cg.shared.global [%0], [%1], 16;"
                 :: "r"(dst), "l"(src));
}
__device__ __forceinline__ void cp_commit() {
    asm volatile("cp.async.commit_group;" ::: "memory");
}
template <int N>
__device__ __forceinline__ void cp_wait() {
    asm volatile("cp.async.wait_group %0;" :: "n"(N) : "memory");
}
__device__ __forceinline__ uint32_t sptr(const void* p) {
    return (uint32_t)__cvta_generic_to_shared(p);
}
__device__ __forceinline__ float bflo(uint32_t u) {
    return __uint_as_float(u << 16);
}
__device__ __forceinline__ float bfhi(uint32_t u) {
    return __uint_as_float(u & 0xffff0000u);
}
__device__ __forceinline__ uint32_t packbf(float a, float b) {
    __nv_bfloat162 t = __floats2bfloat162_rn(a, b);
    return *(uint32_t*)&t;
}

// ---------------------------------------------------------------------------
// Persistent bf16 tensor-core GEMM (R10 validated config):
// C[NPIX,Ntot] = A[NPIX,K] @ Wt[N,K]^T + bias
// BM=128, BN=96, BKC=32; 256 threads = 8 warps (4M x 2N), warp tile 32x48.
// grid = 2*SMs, 2 CTAs/SM; contiguous tile chunks, m-fastest order.
// BRES=1 (K=192): full B tile resident in smem (6 panels); loop stages only A.
// BRES=0 (fc2):   A and B staged per k-stage (3-buf rings).
// MODE: 1 = bf16+GELU out, 2 = bf16 out,
//       3 = fp32 NCHW out with fused residual add (out = x1 + acc+bias).
// ---------------------------------------------------------------------------
#define BM 128
#define BN 96
#define BKC 32
#define MT (NPIX / BM)          // 392 m-tiles
#define ASTG (BM * 64)          // 8192 per A stage
#define BPNL (BN * 64)          // 6144 per B panel
#define SMEM_BRES1 (3 * ASTG + 6 * BPNL)   // 61440
#define SMEM_BRES0 (3 * ASTG + 3 * BPNL)   // 43008

template <int MODE, int BRES>
__global__ __launch_bounds__(256, 2)
void mma_gemm(const bf16* __restrict__ A, const bf16* __restrict__ Bt,
              const float* __restrict__ bias, void* __restrict__ Cout,
              const float* __restrict__ x1aux, int Ntot, int K) {
    extern __shared__ char dsm[];
    const uint32_t aAbase = sptr(dsm);
    const uint32_t aBbase = aAbase + 3 * ASTG;

    int tid = threadIdx.x, lane = tid & 31, wid = tid >> 5;
    int wm = wid & 3, wn = wid >> 2;

    const int S = K / BKC;
    int NT = Ntot / BN;
    int ntiles = MT * NT;
    int base = ntiles / gridDim.x, rem = ntiles % gridDim.x;
    int bidx = blockIdx.x;
    int t0 = bidx * base + (bidx < rem ? bidx : rem);
    int t1 = t0 + base + (bidx < rem ? 1 : 0);
    if (t0 >= t1) return;

    // ldmatrix per-lane address components (validated pattern)
    uint32_t aRow[2], aSw[2];
    int aHalf = lane >> 4;
#pragma unroll
    for (int tm = 0; tm < 2; ++tm) {
        int r = wm * 32 + tm * 16 + (lane & 15);
        aRow[tm] = r * 64;
        aSw[tm]  = (r >> 1) & 3;
    }
    uint32_t bRow[3], bSw[3];
    int bHalf = (lane >> 3) & 1;
#pragma unroll
    for (int p = 0; p < 3; ++p) {
        int r = wn * 48 + p * 16 + ((lane >> 4) << 3) + (lane & 7);
        bRow[p] = r * 64;
        bSw[p]  = (r >> 1) & 3;
    }

    float acc[2][6][4];
#pragma unroll
    for (int i = 0; i < 2; ++i)
#pragma unroll
        for (int j = 0; j < 6; ++j)
#pragma unroll
            for (int l = 0; l < 4; ++l) acc[i][j][l] = 0.f;

    auto compute = [&](uint32_t bA, uint32_t bB) {
#pragma unroll
        for (int kss = 0; kss < 2; ++kss) {
            uint32_t af[2][4], bq[3][4];
#pragma unroll
            for (int tm = 0; tm < 2; ++tm)
                ldsm4(af[tm], bA + aRow[tm]
                      + ((((kss << 1) | aHalf) ^ aSw[tm]) << 4));
#pragma unroll
            for (int p = 0; p < 3; ++p)
                ldsm4(bq[p], bB + bRow[p]
                      + ((((kss << 1) | bHalf) ^ bSw[p]) << 4));
#pragma unroll
            for (int tm = 0; tm < 2; ++tm)
#pragma unroll
                for (int tn = 0; tn < 6; ++tn)
                    mma_bf16(acc[tm][tn], af[tm],
                             bq[tn >> 1][(tn & 1) << 1],
                             bq[tn >> 1][((tn & 1) << 1) + 1]);
        }
    };

    auto epi = [&](int m0, int n0) {
        int q = lane & 3;
#pragma unroll
        for (int tm = 0; tm < 2; ++tm) {
            int r = m0 + wm * 32 + tm * 16 + (lane >> 2);
            size_t base1 = 0, base2 = 0;
            if (MODE == 3) {
                int b1 = r / PIX, yx1 = r % PIX;
                int r2 = r + 8;
                int b2 = r2 / PIX, yx2 = r2 % PIX;
                base1 = (size_t)b1 * (DIM * PIX) + yx1;
                base2 = (size_t)b2 * (DIM * PIX) + yx2;
            }
#pragma unroll
            for (int tn = 0; tn < 6; ++tn) {
                int cl = wn * 48 + tn * 8 + (q << 1);
                float b0 = __ldg(bias + n0 + cl);
                float b1v = __ldg(bias + n0 + cl + 1);
                float v0 = acc[tm][tn][0] + b0;
                float v1 = acc[tm][tn][1] + b1v;
                float v2 = acc[tm][tn][2] + b0;
                float v3 = acc[tm][tn][3] + b1v;
                if (MODE == 1) {
                    v0 = 0.5f * v0 * (1.f + erff(v0 * 0.70710678118654752f));
                    v1 = 0.5f * v1 * (1.f + erff(v1 * 0.70710678118654752f));
                    v2 = 0.5f * v2 * (1.f + erff(v2 * 0.70710678118654752f));
                    v3 = 0.5f * v3 * (1.f + erff(v3 * 0.70710678118654752f));
                }
                if (MODE == 3) {
                    float* O = (float*)Cout;
                    size_t o00 = base1 + (size_t)(n0 + cl) * PIX;
                    size_t o01 = base1 + (size_t)(n0 + cl + 1) * PIX;
                    size_t o10 = base2 + (size_t)(n0 + cl) * PIX;
                    size_t o11 = base2 + (size_t)(n0 + cl + 1) * PIX;
                    O[o00] = x1aux[o00] + v0;
                    O[o01] = x1aux[o01] + v1;
                    O[o10] = x1aux[o10] + v2;
                    O[o11] = x1aux[o11] + v3;
                } else {
                    bf16* C = (bf16*)Cout;
                    *(__nv_bfloat162*)(C + (size_t)r * Ntot + n0 + cl) =
                        __floats2bfloat162_rn(v0, v1);
                    *(__nv_bfloat162*)(C + (size_t)(r + 8) * Ntot + n0 + cl) =
                        __floats2bfloat162_rn(v2, v3);
                }
            }
        }
#pragma unroll
        for (int i = 0; i < 2; ++i)
#pragma unroll
            for (int j = 0; j < 6; ++j)
#pragma unroll
                for (int l = 0; l < 4; ++l) acc[i][j][l] = 0.f;
    };

    if (BRES) {
        // ---- B resident: process tiles grouped by n-index ----
        int t = t0;
        while (t < t1) {
            int nIdx = t / MT;
            int tend = (nIdx + 1) * MT; if (tend > t1) tend = t1;
            int n0 = nIdx * BN;
            __syncthreads();               // drain previous group's smem use
            {   // load all S B panels (S*384 16B-groups)
                int total = S * 384;
                for (int e = tid; e < total; e += 256) {
                    int panel = e / 384;
                    int rg = e - panel * 384;
                    int r = rg >> 2, g4 = rg & 3;
                    uint32_t dst = aBbase + panel * BPNL + r * 64
                                 + ((g4 ^ ((r >> 1) & 3)) << 4);
                    cp16(dst, Bt + (size_t)(n0 + r) * K + panel * BKC + g4 * 8);
                }
                cp_commit();
            }
            int G = (tend - t) * S;
            int sm0 = (t % MT) * BM, sks = 0, sbuf = 0;
            auto stageA = [&]() {
                uint32_t dstb = aAbase + sbuf * ASTG;
                int kc = sks * BKC;
#pragma unroll
                for (int i = 0; i < 2; ++i) {
                    int e = (i << 8) + tid;
                    int row = e >> 2, g4 = e & 3;
                    cp16(dstb + row * 64 + ((g4 ^ ((row >> 1) & 3)) << 4),
                         A + (size_t)(sm0 + row) * K + kc + g4 * 8);
                }
                cp_commit();
                if (++sks == S) { sks = 0; sm0 += BM; }
                if (++sbuf == 3) sbuf = 0;
            };
            stageA(); stageA();            // prologue: 2 stages in flight
            int cm0 = (t % MT) * BM, cks = 0, cbuf = 0;
            for (int g = 0; g < G; ++g) {
                if (g + 1 < G) cp_wait<1>(); else cp_wait<0>();
                __syncthreads();
                if (g + 2 < G) stageA();
                compute(aAbase + cbuf * ASTG, aBbase + cks * BPNL);
                if (++cks == S) { cks = 0; epi(cm0, n0); cm0 += BM; }
                if (++cbuf == 3) cbuf = 0;
            }
            t = tend;
        }
    } else {
        // ---- streaming B (fc2): one continuous pipeline over the chunk ----
        int G = (t1 - t0) * S;
        int sm0 = (t0 % MT) * BM, sn0 = (t0 / MT) * BN, sks = 0, sbuf = 0;
        auto stageAB = [&]() {
            uint32_t dA = aAbase + sbuf * ASTG;
            uint32_t dB = aBbase + sbuf * BPNL;
            int kc = sks * BKC;
#pragma unroll
            for (int i = 0; i < 2; ++i) {
                int e = (i << 8) + tid;
                int row = e >> 2, g4 = e & 3;
                cp16(dA + row * 64 + ((g4 ^ ((row >> 1) & 3)) << 4),
                     A + (size_t)(sm0 + row) * K + kc + g4 * 8);
            }
            {
                int row = tid >> 2, g4 = tid & 3;
                cp16(dB + row * 64 + ((g4 ^ ((row >> 1) & 3)) << 4),
                     Bt + (size_t)(sn0 + row) * K + kc + g4 * 8);
            }
            if (tid < 128) {
                int e = 256 + tid;
                int row = e >> 2, g4 = e & 3;
                cp16(dB + row * 64 + ((g4 ^ ((row >> 1) & 3)) << 4),
                     Bt + (size_t)(sn0 + row) * K + kc + g4 * 8);
            }
            cp_commit();
            if (++sks == S) {
                sks = 0; sm0 += BM;
                if (sm0 == NPIX) { sm0 = 0; sn0 += BN; }
            }
            if (++sbuf == 3) sbuf = 0;
        };
        stageAB(); stageAB();
        int cm0 = (t0 % MT) * BM, cn0 = (t0 / MT) * BN, cks = 0, cbuf = 0;
        for (int g = 0; g < G; ++g) {
            if (g + 1 < G) cp_wait<1>(); else cp_wait<0>();
            __syncthreads();
            if (g + 2 < G) stageAB();
            compute(aAbase + cbuf * ASTG, aBbase + cbuf * BPNL);
            if (++cks == S) {
                cks = 0; epi(cm0, cn0); cm0 += BM;
                if (cm0 == NPIX) { cm0 = 0; cn0 += BN; }
            }
            if (++cbuf == 3) cbuf = 0;
        }
    }
}

// ---------------------------------------------------------------------------
// Bias matrices: [h*4+cls][q(64)][k(64)] = rel_bias + shift-mask, padded = -1e9
// ---------------------------------------------------------------------------
__global__ void bias_build(const float* __restrict__ rel_bias,
                           bf16* __restrict__ bm) {
    int mat = blockIdx.x;            // 0..23
    int h = mat >> 2, cls = mat & 3;
    for (int e = threadIdx.x; e < 4096; e += 256) {
        int qq = e >> 6, kk = e & 63;
        float v = -1e9f;
        if (qq < NWIN && kk < NWIN) {
            int qi = qq / WS, qj = qq % WS, ki = kk / WS, kj = kk % WS;
            int ryq = (cls & 2) ? ((qi < WS - SHIFTV) ? 1 : 2) : 0;
            int rxq = (cls & 1) ? ((qj < WS - SHIFTV) ? 1 : 2) : 0;
            int ryk = (cls & 2) ? ((ki < WS - SHIFTV) ? 1 : 2) : 0;
            int rxk = (cls & 1) ? ((kj < WS - SHIFTV) ? 1 : 2) : 0;
            if (ryq == ryk && rxq == rxk)
                v = rel_bias[((qi - ki + 6) * 13 + (qj - kj + 6)) * HEADS + h];
        }
        bm[mat * 4096 + e] = __float2bfloat16(v);
    }
}

// ---------------------------------------------------------------------------
// K3: MMA windowed attention (unchanged — passing)
// ---------------------------------------------------------------------------
__global__ __launch_bounds__(128)
void attn_mma_kernel(const bf16* __restrict__ qkv,
                     const bf16* __restrict__ biasmat,
                     bf16* __restrict__ ao) {
    __shared__ __align__(16) bf16 sm[3 * 64 * 32];   // Q,K,V: 64 rows x 64B each

    int blk = blockIdx.x;
    int h = blk % HEADS, w = blk / HEADS;
    int widx = w & 63;
    int wi = widx >> 3, wj = widx & 7;
    int cls = ((wi == 7) ? 2 : 0) + ((wj == 7) ? 1 : 0);
    const bf16* bm = biasmat + (size_t)(h * 4 + cls) * 4096;
    int r0 = w * NWIN;
    int tid = threadIdx.x, lane = tid & 31, wid = tid >> 5;

    uint32_t sb = sptr(sm);

    const uint4 z4 = make_uint4(0, 0, 0, 0);
    for (int e = tid; e < 768; e += 128) {
        int mat = e >> 8;               // 0=Q 1=K 2=V
        int rg  = e & 255;
        int row = rg >> 2, g = rg & 3;
        uint32_t dst = sb + mat * 4096 + row * 64 + ((g ^ ((row >> 1) & 3)) << 4);
        uint4 v = z4;
        if (row < NWIN)
            v = *(const uint4*)(qkv + (size_t)(r0 + row) * 576 + mat * 192
                                + h * HD + g * 8);
        *(uint4*)((char*)sm + (dst - sb)) = v;
    }
    __syncthreads();

    int qbase = wid * 16;
    int rw = lane & 7;

    float sacc[8][4];
#pragma unroll
    for (int n = 0; n < 8; ++n)
#pragma unroll
        for (int l = 0; l < 4; ++l) sacc[n][l] = 0.f;

    int aHalf = lane >> 4;
    int arow = qbase + (lane & 15);
    uint32_t aAddrBase = sb + arow * 64;
    uint32_t aSw = (arow >> 1) & 3;
    int bHalf = (lane >> 3) & 1;

#pragma unroll
    for (int c = 0; c < 2; ++c) {
        uint32_t af[4];
        ldsm4(af, aAddrBase + ((((c << 1) | aHalf) ^ aSw) << 4));
#pragma unroll
        for (int t = 0; t < 4; ++t) {
            int brow = t * 16 + ((lane >> 4) << 3) + rw;
            uint32_t bq[4];
            ldsm4(bq, sb + 4096 + brow * 64
                  + ((((c << 1) | bHalf) ^ ((brow >> 1) & 3)) << 4));
            mma_bf16(sacc[2 * t],     af, bq[0], bq[1]);
            mma_bf16(sacc[2 * t + 1], af, bq[2], bq[3]);
        }
    }

    int rA = qbase + (lane >> 2);
    int rB = rA + 8;
    const bf16* bmA = bm + rA * 64 + ((lane & 3) << 1);
    const bf16* bmB = bm + rB * 64 + ((lane & 3) << 1);

    float mx0 = -1e30f, mx1 = -1e30f;
#pragma unroll
    for (int n = 0; n < 8; ++n) {
        uint32_t bb0 = *(const uint32_t*)(bmA + n * 8);
        uint32_t bb1 = *(const uint32_t*)(bmB + n * 8);
        sacc[n][0] = sacc[n][0] * SCALE_Q + bflo(bb0);
        sacc[n][1] = sacc[n][1] * SCALE_Q + bfhi(bb0);
        sacc[n][2] = sacc[n][2] * SCALE_Q + bflo(bb1);
        sacc[n][3] = sacc[n][3] * SCALE_Q + bfhi(bb1);
        mx0 = fmaxf(mx0, fmaxf(sacc[n][0], sacc[n][1]));
        mx1 = fmaxf(mx1, fmaxf(sacc[n][2], sacc[n][3]));
    }
    mx0 = fmaxf(mx0, __shfl_xor_sync(0xffffffffu, mx0, 1));
    mx0 = fmaxf(mx0, __shfl_xor_sync(0xffffffffu, mx0, 2));
    mx1 = fmaxf(mx1, __shfl_xor_sync(0xffffffffu, mx1, 1));
    mx1 = fmaxf(mx1, __shfl_xor_sync(0xffffffffu, mx1, 2));

    float sum0 = 0.f, sum1 = 0.f;
#pragma unroll
    for (int n = 0; n < 8; ++n) {
        sacc[n][0] = __expf(sacc[n][0] - mx0);
        sacc[n][1] = __expf(sacc[n][1] - mx0);
        sacc[n][2] = __expf(sacc[n][2] - mx1);
        sacc[n][3] = __expf(sacc[n][3] - mx1);
        sum0 += sacc[n][0] + sacc[n][1];
        sum1 += sacc[n][2] + sacc[n][3];
    }
    sum0 += __shfl_xor_sync(0xffffffffu, sum0, 1);
    sum0 += __shfl_xor_sync(0xffffffffu, sum0, 2);
    sum1 += __shfl_xor_sync(0xffffffffu, sum1, 1);
    sum1 += __shfl_xor_sync(0xffffffffu, sum1, 2);
    float inv0 = 1.f / sum0, inv1 = 1.f / sum1;

    uint32_t pA[8], pB[8];
#pragma unroll
    for (int n = 0; n < 8; ++n) {
        pA[n] = packbf(sacc[n][0] * inv0, sacc[n][1] * inv0);
        pB[n] = packbf(sacc[n][2] * inv1, sacc[n][3] * inv1);
    }

    float oacc[4][4];
#pragma unroll
    for (int d = 0; d < 4; ++d)
#pragma unroll
        for (int l = 0; l < 4; ++l) oacc[d][l] = 0.f;

#pragma unroll
    for (int kc = 0; kc < 4; ++kc) {
        uint32_t af[4] = { pA[2 * kc], pB[2 * kc], pA[2 * kc + 1], pB[2 * kc + 1] };
        int vrow = kc * 16 + (((lane >> 3) & 1) << 3) + rw;
        uint32_t vswz = (vrow >> 1) & 3;
        int ghalf = (lane >> 4) & 1;
        uint32_t v01[4], v23[4];
        ldsm4t(v01, sb + 8192 + vrow * 64 + (((0 + ghalf) ^ vswz) << 4));
        ldsm4t(v23, sb + 8192 + vrow * 64 + (((2 + ghalf) ^ vswz) << 4));
        mma_bf16(oacc[0], af, v01[0], v01[1]);
        mma_bf16(oacc[1], af, v01[2], v01[3]);
        mma_bf16(oacc[2], af, v23[0], v23[1]);
        mma_bf16(oacc[3], af, v23[2], v23[3]);
    }

    int colb = h * HD + ((lane & 3) << 1);
    if (rA < NWIN) {
        bf16* op = ao + (size_t)(r0 + rA) * DIM + colb;
#pragma unroll
        for (int d = 0; d < 4; ++d)
            *(uint32_t*)(op + d * 8) = packbf(oacc[d][0], oacc[d][1]);
    }
    if (rB < NWIN) {
        bf16* op = ao + (size_t)(r0 + rB) * DIM + colb;
#pragma unroll
        for (int d = 0; d < 4; ++d)
            *(uint32_t*)(op + d * 8) = packbf(oacc[d][2], oacc[d][3]);
    }
}

// ---------------------------------------------------------------------------
// All 4 weight transposes (+bf16 convert) in ONE launch
// ---------------------------------------------------------------------------
__global__ void transpose_all(const float* __restrict__ w0, const float* __restrict__ w1,
                              const float* __restrict__ w2, const float* __restrict__ w3,
                              bf16* __restrict__ t0, bf16* __restrict__ t1,
                              bf16* __restrict__ t2, bf16* __restrict__ t3) {
    __shared__ float t[32][33];
    int bid = blockIdx.x;
    const float* W; bf16* Wt; int K, N, tn, tk;
    if (bid < 108)      { W = w0; Wt = t0; K = 192; N = 576; tn = bid % 18; tk = bid / 18; }
    else if (bid < 144) { bid -= 108; W = w1; Wt = t1; K = 192; N = 192; tn = bid % 6;  tk = bid / 6; }
    else if (bid < 288) { bid -= 144; W = w2; Wt = t2; K = 192; N = 768; tn = bid % 24; tk = bid / 24; }
    else                { bid -= 288; W = w3; Wt = t3; K = 768; N = 192; tn = bid % 6;  tk = bid / 6; }
    int k0 = tk * 32, n0 = tn * 32;
    int tx = threadIdx.x, ty = threadIdx.y;
#pragma unroll
    for (int i = 0; i < 32; i += 8)
        t[ty + i][tx] = W[(size_t)(k0 + ty + i) * N + n0 + tx];
    __syncthreads();
#pragma unroll
    for (int i = 0; i < 32; i += 8)
        Wt[(size_t)(n0 + ty + i) * K + k0 + tx] = __float2bfloat16(t[tx][ty + i]);
}

// ---------------------------------------------------------------------------
// K1: LayerNorm1 + roll(-3,-3) + window partition -> bf16 win
// ---------------------------------------------------------------------------
__global__ __launch_bounds__(256)
void ln1_win_kernel(const float* __restrict__ x,
                    const float* __restrict__ gam,
                    const float* __restrict__ bet,
                    bf16* __restrict__ win) {
    __shared__ float sm[32][193];
    int p0  = blockIdx.x * 32;
    int b   = p0 / PIX, yx0 = p0 % PIX;
    int tid = threadIdx.x, warp = tid >> 5, lane = tid & 31;

    const float* xb = x + (size_t)b * (DIM * PIX) + yx0;
#pragma unroll
    for (int cc = 0; cc < 24; ++cc) {
        int c = warp + cc * 8;
        sm[lane][c] = xb[(size_t)c * PIX + lane];
    }
    __syncthreads();

#pragma unroll
    for (int t = 0; t < 4; ++t) {
        int pix = warp * 4 + t;
        float v[6], s = 0.f, sq = 0.f;
#pragma unroll
        for (int j = 0; j < 6; ++j) {
            float u = sm[pix][lane + j * 32];
            v[j] = u; s += u; sq += u * u;
        }
#pragma unroll
        for (int o = 16; o; o >>= 1) {
            s  += __shfl_xor_sync(0xffffffffu, s,  o);
            sq += __shfl_xor_sync(0xffffffffu, sq, o);
        }
        float mu   = s * (1.f / DIM);
        float var  = sq * (1.f / DIM) - mu * mu;
        float rstd = rsqrtf(var + 1e-5f);

        int yx = yx0 + pix;
        int y  = yx / HW, xx = yx % HW;
        int y2 = (y  + HW - SHIFTV) % HW;
        int x2 = (xx + HW - SHIFTV) % HW;
        int r  = b * PIX + ((y2 / WS) * NW_GRID + (x2 / WS)) * NWIN
               + (y2 % WS) * WS + (x2 % WS);
        bf16* wp = win + (size_t)r * DIM;
#pragma unroll
        for (int j = 0; j < 6; ++j) {
            int c = lane + j * 32;
            wp[c] = __float2bfloat16((v[j] - mu) * rstd * gam[c] + bet[c]);
        }
    }
}

// ---------------------------------------------------------------------------
// K5: x1 = x + window-reverse(proj_out bf16);  h2 = LN2(x1) -> bf16
// ---------------------------------------------------------------------------
__global__ __launch_bounds__(256)
void addln2_kernel(const float* __restrict__ x,
                   const bf16* __restrict__ po,
                   const float* __restrict__ gam,
                   const float* __restrict__ bet,
                   float* __restrict__ x1,
                   bf16* __restrict__ h2) {
    __shared__ float sm[32][193];
    int p0  = blockIdx.x * 32;
    int b   = p0 / PIX, yx0 = p0 % PIX;
    int tid = threadIdx.x, warp = tid >> 5, lane = tid & 31;

#pragma unroll
    for (int t = 0; t < 4; ++t) {
        int pix = warp * 4 + t;
        int yx = yx0 + pix;
        int y  = yx / HW, xx = yx % HW;
        int y2 = (y  + HW - SHIFTV) % HW;
        int x2 = (xx + HW - SHIFTV) % HW;
        int r  = b * PIX + ((y2 / WS) * NW_GRID + (x2 / WS)) * NWIN
               + (y2 % WS) * WS + (x2 % WS);
        const bf16* pp = po + (size_t)r * DIM;
#pragma unroll
        for (int j = 0; j < 6; ++j) {
            int c = lane + j * 32;
            sm[pix][c] = __bfloat162float(pp[c]);
        }
    }
    __syncthreads();

    const float* xb = x  + (size_t)b * (DIM * PIX) + yx0;
    float*       xo = x1 + (size_t)b * (DIM * PIX) + yx0;
#pragma unroll
    for (int cc = 0; cc < 24; ++cc) {
        int c = warp + cc * 8;
        float v = xb[(size_t)c * PIX + lane] + sm[lane][c];
        xo[(size_t)c * PIX + lane] = v;
        sm[lane][c] = v;
    }
    __syncthreads();

#pragma unroll
    for (int t = 0; t < 4; ++t) {
        int pix = warp * 4 + t;
        float v[6], s = 0.f, sq = 0.f;
#pragma unroll
        for (int j = 0; j < 6; ++j) {
            float u = sm[pix][lane + j * 32];
            v[j] = u; s += u; sq += u * u;
        }
#pragma unroll
        for (int o = 16; o; o >>= 1) {
            s  += __shfl_xor_sync(0xffffffffu, s,  o);
            sq += __shfl_xor_sync(0xffffffffu, sq, o);
        }
        float mu   = s * (1.f / DIM);
        float var  = sq * (1.f / DIM) - mu * mu;
        float rstd = rsqrtf(var + 1e-5f);

        bf16* hp = h2 + (size_t)(p0 + pix) * DIM;
#pragma unroll
        for (int j = 0; j < 6; ++j) {
            int c = lane + j * 32;
            hp[c] = __float2bfloat16((v[j] - mu) * rstd * gam[c] + bet[c]);
        }
    }
}

// ---------------------------------------------------------------------------
// Launch
// ---------------------------------------------------------------------------
extern "C" void kernel_launch(void* const* d_in, const int* in_sizes, int n_in,
                              void* d_out, int out_size) {
    const float* x      = (const float*)d_in[0];
    const float* n1g    = (const float*)d_in[1];
    const float* n1b    = (const float*)d_in[2];
    const float* qkv_w  = (const float*)d_in[3];
    const float* qkv_b  = (const float*)d_in[4];
    const float* proj_w = (const float*)d_in[5];
    const float* proj_b = (const float*)d_in[6];
    const float* relb   = (const float*)d_in[7];
    const float* n2g    = (const float*)d_in[8];
    const float* n2b    = (const float*)d_in[9];
    const float* fc1_w  = (const float*)d_in[10];
    const float* fc1_b  = (const float*)d_in[11];
    const float* fc2_w  = (const float*)d_in[12];
    const float* fc2_b  = (const float*)d_in[13];
    float* out = (float*)d_out;

    bf16 *ba, *bb, *bg, *bpo, *wqkv, *wproj, *wfc1, *wfc2, *bmat;
    float *bx1;
    cudaGetSymbolAddress((void**)&ba,   gb_a);
    cudaGetSymbolAddress((void**)&bb,   gb_b);
    cudaGetSymbolAddress((void**)&bg,   gb_big);
    cudaGetSymbolAddress((void**)&bpo,  gb_po);
    cudaGetSymbolAddress((void**)&bx1,  g_x1);
    cudaGetSymbolAddress((void**)&wqkv, g_qkv_wt);
    cudaGetSymbolAddress((void**)&wproj,g_proj_wt);
    cudaGetSymbolAddress((void**)&wfc1, g_fc1_wt);
    cudaGetSymbolAddress((void**)&wfc2, g_fc2_wt);
    cudaGetSymbolAddress((void**)&bmat, g_biasmat);

    cudaFuncSetAttribute(mma_gemm<2,1>, cudaFuncAttributeMaxDynamicSharedMemorySize, SMEM_BRES1);
    cudaFuncSetAttribute(mma_gemm<1,1>, cudaFuncAttributeMaxDynamicSharedMemorySize, SMEM_BRES1);
    cudaFuncSetAttribute(mma_gemm<3,0>, cudaFuncAttributeMaxDynamicSharedMemorySize, SMEM_BRES0);

    int dev = 0, nsm = 148;
    cudaGetDevice(&dev);
    cudaDeviceGetAttribute(&nsm, cudaDevAttrMultiProcessorCount, dev);
    int grid = nsm * 2;

    // 0) weight transposes + bias/mask matrices
    transpose_all<<<432, dim3(32, 8)>>>(qkv_w, proj_w, fc1_w, fc2_w,
                                        wqkv, wproj, wfc1, wfc2);
    bias_build<<<24, 256>>>(relb, bmat);

    // 1) LN1 + roll + window partition -> ba = win[50176,192] bf16
    ln1_win_kernel<<<NPIX / 32, 256>>>(x, n1g, n1b, ba);

    // 2) QKV GEMM -> bg[50176,576] bf16
    mma_gemm<2,1><<<grid, 256, SMEM_BRES1>>>(ba, wqkv, qkv_b, bg,
                                             nullptr, 576, 192);
    // 3) MMA attention -> bb[50176,192] bf16
    attn_mma_kernel<<<1024 * HEADS, 128>>>(bg, bmat, bb);

    // 4) proj GEMM -> bpo bf16
    mma_gemm<2,1><<<grid, 256, SMEM_BRES1>>>(bb, wproj, proj_b, bpo,
                                             nullptr, 192, 192);
    // 5) residual + LN2 -> bx1 (NCHW fp32), ba = h2 bf16
    addln2_kernel<<<NPIX / 32, 256>>>(x, bpo, n2g, n2b, bx1, ba);

    // 6) fc1 + GELU -> bg[50176,768] bf16
    mma_gemm<1,1><<<grid, 256, SMEM_BRES1>>>(ba, wfc1, fc1_b, bg,
                                             nullptr, 768, 192);
    // 7) fc2 + fused residual -> out (NCHW fp32)
    mma_gemm<3,0><<<grid, 256, SMEM_BRES0>>>(bg, wfc2, fc2_b, out,
                                             bx1, 192, 768);
}

// round 14
// speedup vs baseline: 1.1515x; 1.0212x over previous
#include <cuda_runtime.h>
#include <cuda_bf16.h>
#include <math.h>
#include <stdint.h>

// ---------------------------------------------------------------------------
// Problem constants
// ---------------------------------------------------------------------------
#define BATCH   16
#define DIM     192
#define HW      56
#define PIX     3136            // 56*56
#define NPIX    50176           // 16*3136
#define WS      7
#define SHIFTV  3
#define NWIN    49
#define HEADS   6
#define HD      32
#define NW_GRID 8
#define SCALE_Q 0.1767766952966369f

typedef __nv_bfloat16 bf16;

// ---------------------------------------------------------------------------
// Scratch buffers (allocation-free: device globals)
// ---------------------------------------------------------------------------
__device__ __align__(128) bf16  gb_a   [NPIX * DIM];   // win (ln1 out) / h2 (ln2 out)
__device__ __align__(128) bf16  gb_b   [NPIX * DIM];   // attn out
__device__ __align__(128) bf16  gb_big [NPIX * 768];   // qkv out (576 used) / fc1 out
__device__ __align__(128) bf16  gb_po  [NPIX * DIM];   // proj out (bf16)
// transposed bf16 weights Wt[N][K]
__device__ __align__(128) bf16 g_qkv_wt [576 * 192];
__device__ __align__(128) bf16 g_proj_wt[192 * 192];
__device__ __align__(128) bf16 g_fc1_wt [768 * 192];
__device__ __align__(128) bf16 g_fc2_wt [192 * 768];
// precomputed attention bias+mask matrices: [head*4+cls][64][64] bf16
__device__ __align__(128) bf16 g_biasmat[24 * 64 * 64];

// ---------------------------------------------------------------------------
// PTX helpers
// ---------------------------------------------------------------------------
__device__ __forceinline__ void mma_bf16(float c[4], const uint32_t a[4],
                                         const uint32_t b0, const uint32_t b1) {
    asm volatile(
        "mma.sync.aligned.m16n8k16.row.col.f32.bf16.bf16.f32 "
        "{%0,%1,%2,%3}, {%4,%5,%6,%7}, {%8,%9}, {%0,%1,%2,%3};"
        : "+f"(c[0]), "+f"(c[1]), "+f"(c[2]), "+f"(c[3])
        : "r"(a[0]), "r"(a[1]), "r"(a[2]), "r"(a[3]),
          "r"(b0), "r"(b1));
}
__device__ __forceinline__ void ldsm4(uint32_t r[4], uint32_t addr) {
    asm volatile("ldmatrix.sync.aligned.m8n8.x4.shared.b16 {%0,%1,%2,%3}, [%4];"
                 : "=r"(r[0]), "=r"(r[1]), "=r"(r[2]), "=r"(r[3]) : "r"(addr));
}
__device__ __forceinline__ void ldsm4t(uint32_t r[4], uint32_t addr) {
    asm volatile("ldmatrix.sync.aligned.m8n8.x4.trans.shared.b16 {%0,%1,%2,%3}, [%4];"
                 : "=r"(r[0]), "=r"(r[1]), "=r"(r[2]), "=r"(r[3]) : "r"(addr));
}
__device__ __forceinline__ void cp16(uint32_t dst, const void* src) {
    asm volatile("cp.async.cg.shared.global [%0], [%1], 16;"
                 :: "r"(dst), "l"(src));
}
__device__ __forceinline__ void cp_commit() {
    asm volatile("cp.async.commit_group;" ::: "memory");
}
template <int N>
__device__ __forceinline__ void cp_wait() {
    asm volatile("cp.async.wait_group %0;" :: "n"(N) : "memory");
}
__device__ __forceinline__ uint32_t sptr(const void* p) {
    return (uint32_t)__cvta_generic_to_shared(p);
}
__device__ __forceinline__ float bflo(uint32_t u) {
    return __uint_as_float(u << 16);
}
__device__ __forceinline__ float bfhi(uint32_t u) {
    return __uint_as_float(u & 0xffff0000u);
}
__device__ __forceinline__ uint32_t packbf(float a, float b) {
    __nv_bfloat162 t = __floats2bfloat162_rn(a, b);
    return *(uint32_t*)&t;
}

// ---------------------------------------------------------------------------
// Persistent bf16 tensor-core GEMM (validated R10/R12 config):
// C[NPIX,Ntot] = A[NPIX,K] @ Wt[N,K]^T + bias
// BM=128, BN=96, BKC=32; 8 warps (4M x 2N), warp tile 32x48; 2 CTAs/SM.
// BRES=1 (K=192): full B tile resident in smem (6 panels); loop stages only A.
// BRES=0 (fc2):   A and B staged per k-stage (3-buf rings).
// MODE: 1 = bf16+GELU out, 2 = bf16 out,
//       3 = fp32 NCHW out, fused DOUBLE residual:
//           out = x + window_reverse(po) + (acc + bias)
// ---------------------------------------------------------------------------
#define BM 128
#define BN 96
#define BKC 32
#define MT (NPIX / BM)          // 392 m-tiles
#define ASTG (BM * 64)          // 8192 per A stage
#define BPNL (BN * 64)          // 6144 per B panel
#define SMEM_BRES1 (3 * ASTG + 6 * BPNL)   // 61440
#define SMEM_BRES0 (3 * ASTG + 3 * BPNL)   // 43008

template <int MODE, int BRES>
__global__ __launch_bounds__(256, 2)
void mma_gemm(const bf16* __restrict__ A, const bf16* __restrict__ Bt,
              const float* __restrict__ bias, void* __restrict__ Cout,
              const float* __restrict__ xaux, const bf16* __restrict__ poaux,
              int Ntot, int K) {
    extern __shared__ char dsm[];
    const uint32_t aAbase = sptr(dsm);
    const uint32_t aBbase = aAbase + 3 * ASTG;

    int tid = threadIdx.x, lane = tid & 31, wid = tid >> 5;
    int wm = wid & 3, wn = wid >> 2;

    const int S = K / BKC;
    int NT = Ntot / BN;
    int ntiles = MT * NT;
    int base = ntiles / gridDim.x, rem = ntiles % gridDim.x;
    int bidx = blockIdx.x;
    int t0 = bidx * base + (bidx < rem ? bidx : rem);
    int t1 = t0 + base + (bidx < rem ? 1 : 0);
    if (t0 >= t1) return;

    // ldmatrix per-lane address components (validated pattern)
    uint32_t aRow[2], aSw[2];
    int aHalf = lane >> 4;
#pragma unroll
    for (int tm = 0; tm < 2; ++tm) {
        int r = wm * 32 + tm * 16 + (lane & 15);
        aRow[tm] = r * 64;
        aSw[tm]  = (r >> 1) & 3;
    }
    uint32_t bRow[3], bSw[3];
    int bHalf = (lane >> 3) & 1;
#pragma unroll
    for (int p = 0; p < 3; ++p) {
        int r = wn * 48 + p * 16 + ((lane >> 4) << 3) + (lane & 7);
        bRow[p] = r * 64;
        bSw[p]  = (r >> 1) & 3;
    }

    float acc[2][6][4];
#pragma unroll
    for (int i = 0; i < 2; ++i)
#pragma unroll
        for (int j = 0; j < 6; ++j)
#pragma unroll
            for (int l = 0; l < 4; ++l) acc[i][j][l] = 0.f;

    auto compute = [&](uint32_t bA, uint32_t bB) {
#pragma unroll
        for (int kss = 0; kss < 2; ++kss) {
            uint32_t af[2][4], bq[3][4];
#pragma unroll
            for (int tm = 0; tm < 2; ++tm)
                ldsm4(af[tm], bA + aRow[tm]
                      + ((((kss << 1) | aHalf) ^ aSw[tm]) << 4));
#pragma unroll
            for (int p = 0; p < 3; ++p)
                ldsm4(bq[p], bB + bRow[p]
                      + ((((kss << 1) | bHalf) ^ bSw[p]) << 4));
#pragma unroll
            for (int tm = 0; tm < 2; ++tm)
#pragma unroll
                for (int tn = 0; tn < 6; ++tn)
                    mma_bf16(acc[tm][tn], af[tm],
                             bq[tn >> 1][(tn & 1) << 1],
                             bq[tn >> 1][((tn & 1) << 1) + 1]);
        }
    };

    auto epi = [&](int m0, int n0) {
        int q = lane & 3;
#pragma unroll
        for (int tm = 0; tm < 2; ++tm) {
            int r = m0 + wm * 32 + tm * 16 + (lane >> 2);
            size_t base1 = 0, base2 = 0;
            int wr1 = 0, wr2 = 0;
            if (MODE == 3) {
                int r2 = r + 8;
                int b1 = r / PIX, yx1 = r % PIX;
                int b2 = r2 / PIX, yx2 = r2 % PIX;
                base1 = (size_t)b1 * (DIM * PIX) + yx1;
                base2 = (size_t)b2 * (DIM * PIX) + yx2;
                int y1 = yx1 / HW, xp1 = yx1 % HW;
                int yy1 = (y1 + HW - SHIFTV) % HW, xx1 = (xp1 + HW - SHIFTV) % HW;
                wr1 = b1 * PIX + ((yy1 / WS) * NW_GRID + xx1 / WS) * NWIN
                    + (yy1 % WS) * WS + (xx1 % WS);
                int y2 = yx2 / HW, xp2 = yx2 % HW;
                int yy2 = (y2 + HW - SHIFTV) % HW, xx2 = (xp2 + HW - SHIFTV) % HW;
                wr2 = b2 * PIX + ((yy2 / WS) * NW_GRID + xx2 / WS) * NWIN
                    + (yy2 % WS) * WS + (xx2 % WS);
            }
#pragma unroll
            for (int tn = 0; tn < 6; ++tn) {
                int cl = wn * 48 + tn * 8 + (q << 1);
                float b0 = __ldg(bias + n0 + cl);
                float b1v = __ldg(bias + n0 + cl + 1);
                float v0 = acc[tm][tn][0] + b0;
                float v1 = acc[tm][tn][1] + b1v;
                float v2 = acc[tm][tn][2] + b0;
                float v3 = acc[tm][tn][3] + b1v;
                if (MODE == 1) {
                    v0 = 0.5f * v0 * (1.f + erff(v0 * 0.70710678118654752f));
                    v1 = 0.5f * v1 * (1.f + erff(v1 * 0.70710678118654752f));
                    v2 = 0.5f * v2 * (1.f + erff(v2 * 0.70710678118654752f));
                    v3 = 0.5f * v3 * (1.f + erff(v3 * 0.70710678118654752f));
                }
                if (MODE == 3) {
                    uint32_t pw1 = *(const uint32_t*)(poaux + (size_t)wr1 * DIM + n0 + cl);
                    uint32_t pw2 = *(const uint32_t*)(poaux + (size_t)wr2 * DIM + n0 + cl);
                    float* O = (float*)Cout;
                    size_t o00 = base1 + (size_t)(n0 + cl) * PIX;
                    size_t o01 = base1 + (size_t)(n0 + cl + 1) * PIX;
                    size_t o10 = base2 + (size_t)(n0 + cl) * PIX;
                    size_t o11 = base2 + (size_t)(n0 + cl + 1) * PIX;
                    O[o00] = xaux[o00] + bflo(pw1) + v0;
                    O[o01] = xaux[o01] + bfhi(pw1) + v1;
                    O[o10] = xaux[o10] + bflo(pw2) + v2;
                    O[o11] = xaux[o11] + bfhi(pw2) + v3;
                } else {
                    bf16* C = (bf16*)Cout;
                    *(__nv_bfloat162*)(C + (size_t)r * Ntot + n0 + cl) =
                        __floats2bfloat162_rn(v0, v1);
                    *(__nv_bfloat162*)(C + (size_t)(r + 8) * Ntot + n0 + cl) =
                        __floats2bfloat162_rn(v2, v3);
                }
            }
        }
#pragma unroll
        for (int i = 0; i < 2; ++i)
#pragma unroll
            for (int j = 0; j < 6; ++j)
#pragma unroll
                for (int l = 0; l < 4; ++l) acc[i][j][l] = 0.f;
    };

    if (BRES) {
        // ---- B resident: process tiles grouped by n-index ----
        int t = t0;
        while (t < t1) {
            int nIdx = t / MT;
            int tend = (nIdx + 1) * MT; if (tend > t1) tend = t1;
            int n0 = nIdx * BN;
            __syncthreads();               // drain previous group's smem use
            {   // load all S B panels (S*384 16B-groups)
                int total = S * 384;
                for (int e = tid; e < total; e += 256) {
                    int panel = e / 384;
                    int rg = e - panel * 384;
                    int r = rg >> 2, g4 = rg & 3;
                    uint32_t dst = aBbase + panel * BPNL + r * 64
                                 + ((g4 ^ ((r >> 1) & 3)) << 4);
                    cp16(dst, Bt + (size_t)(n0 + r) * K + panel * BKC + g4 * 8);
                }
                cp_commit();
            }
            int G = (tend - t) * S;
            int sm0 = (t % MT) * BM, sks = 0, sbuf = 0;
            auto stageA = [&]() {
                uint32_t dstb = aAbase + sbuf * ASTG;
                int kc = sks * BKC;
#pragma unroll
                for (int i = 0; i < 2; ++i) {
                    int e = (i << 8) + tid;
                    int row = e >> 2, g4 = e & 3;
                    cp16(dstb + row * 64 + ((g4 ^ ((row >> 1) & 3)) << 4),
                         A + (size_t)(sm0 + row) * K + kc + g4 * 8);
                }
                cp_commit();
                if (++sks == S) { sks = 0; sm0 += BM; }
                if (++sbuf == 3) sbuf = 0;
            };
            stageA(); stageA();            // prologue: 2 stages in flight
            int cm0 = (t % MT) * BM, cks = 0, cbuf = 0;
            for (int g = 0; g < G; ++g) {
                if (g + 1 < G) cp_wait<1>(); else cp_wait<0>();
                __syncthreads();
                if (g + 2 < G) stageA();
                compute(aAbase + cbuf * ASTG, aBbase + cks * BPNL);
                if (++cks == S) { cks = 0; epi(cm0, n0); cm0 += BM; }
                if (++cbuf == 3) cbuf = 0;
            }
            t = tend;
        }
    } else {
        // ---- streaming B (fc2): one continuous pipeline over the chunk ----
        int G = (t1 - t0) * S;
        int sm0 = (t0 % MT) * BM, sn0 = (t0 / MT) * BN, sks = 0, sbuf = 0;
        auto stageAB = [&]() {
            uint32_t dA = aAbase + sbuf * ASTG;
            uint32_t dB = aBbase + sbuf * BPNL;
            int kc = sks * BKC;
#pragma unroll
            for (int i = 0; i < 2; ++i) {
                int e = (i << 8) + tid;
                int row = e >> 2, g4 = e & 3;
                cp16(dA + row * 64 + ((g4 ^ ((row >> 1) & 3)) << 4),
                     A + (size_t)(sm0 + row) * K + kc + g4 * 8);
            }
            {
                int row = tid >> 2, g4 = tid & 3;
                cp16(dB + row * 64 + ((g4 ^ ((row >> 1) & 3)) << 4),
                     Bt + (size_t)(sn0 + row) * K + kc + g4 * 8);
            }
            if (tid < 128) {
                int e = 256 + tid;
                int row = e >> 2, g4 = e & 3;
                cp16(dB + row * 64 + ((g4 ^ ((row >> 1) & 3)) << 4),
                     Bt + (size_t)(sn0 + row) * K + kc + g4 * 8);
            }
            cp_commit();
            if (++sks == S) {
                sks = 0; sm0 += BM;
                if (sm0 == NPIX) { sm0 = 0; sn0 += BN; }
            }
            if (++sbuf == 3) sbuf = 0;
        };
        stageAB(); stageAB();
        int cm0 = (t0 % MT) * BM, cn0 = (t0 / MT) * BN, cks = 0, cbuf = 0;
        for (int g = 0; g < G; ++g) {
            if (g + 1 < G) cp_wait<1>(); else cp_wait<0>();
            __syncthreads();
            if (g + 2 < G) stageAB();
            compute(aAbase + cbuf * ASTG, aBbase + cbuf * BPNL);
            if (++cks == S) {
                cks = 0; epi(cm0, cn0); cm0 += BM;
                if (cm0 == NPIX) { cm0 = 0; cn0 += BN; }
            }
            if (++cbuf == 3) cbuf = 0;
        }
    }
}

// ---------------------------------------------------------------------------
// Setup: 4 weight transposes (+bf16) AND bias/mask matrices in ONE launch.
// Blocks 0..431: transposes. Blocks 432..455: bias matrices.
// ---------------------------------------------------------------------------
__global__ void setup_all(const float* __restrict__ w0, const float* __restrict__ w1,
                          const float* __restrict__ w2, const float* __restrict__ w3,
                          bf16* __restrict__ t0, bf16* __restrict__ t1,
                          bf16* __restrict__ t2, bf16* __restrict__ t3,
                          const float* __restrict__ rel_bias,
                          bf16* __restrict__ bm) {
    int bid = blockIdx.x;
    int ftid = threadIdx.y * 32 + threadIdx.x;
    if (bid >= 432) {
        int mat = bid - 432;             // 0..23
        int h = mat >> 2, cls = mat & 3;
        for (int e = ftid; e < 4096; e += 256) {
            int qq = e >> 6, kk = e & 63;
            float v = -1e9f;
            if (qq < NWIN && kk < NWIN) {
                int qi = qq / WS, qj = qq % WS, ki = kk / WS, kj = kk % WS;
                int ryq = (cls & 2) ? ((qi < WS - SHIFTV) ? 1 : 2) : 0;
                int rxq = (cls & 1) ? ((qj < WS - SHIFTV) ? 1 : 2) : 0;
                int ryk = (cls & 2) ? ((ki < WS - SHIFTV) ? 1 : 2) : 0;
                int rxk = (cls & 1) ? ((kj < WS - SHIFTV) ? 1 : 2) : 0;
                if (ryq == ryk && rxq == rxk)
                    v = rel_bias[((qi - ki + 6) * 13 + (qj - kj + 6)) * HEADS + h];
            }
            bm[mat * 4096 + e] = __float2bfloat16(v);
        }
        return;
    }
    __shared__ float t[32][33];
    const float* W; bf16* Wt; int K, N, tn, tk;
    if (bid < 108)      { W = w0; Wt = t0; K = 192; N = 576; tn = bid % 18; tk = bid / 18; }
    else if (bid < 144) { bid -= 108; W = w1; Wt = t1; K = 192; N = 192; tn = bid % 6;  tk = bid / 6; }
    else if (bid < 288) { bid -= 144; W = w2; Wt = t2; K = 192; N = 768; tn = bid % 24; tk = bid / 24; }
    else                { bid -= 288; W = w3; Wt = t3; K = 768; N = 192; tn = bid % 6;  tk = bid / 6; }
    int k0 = tk * 32, n0 = tn * 32;
    int tx = threadIdx.x, ty = threadIdx.y;
#pragma unroll
    for (int i = 0; i < 32; i += 8)
        t[ty + i][tx] = W[(size_t)(k0 + ty + i) * N + n0 + tx];
    __syncthreads();
#pragma unroll
    for (int i = 0; i < 32; i += 8)
        Wt[(size_t)(n0 + ty + i) * K + k0 + tx] = __float2bfloat16(t[tx][ty + i]);
}

// ---------------------------------------------------------------------------
// K3: MMA windowed attention. No max-subtraction (scores are tiny; softmax is
// shift-invariant). Key column block n=7 (keys 56-63) fully padded -> P=0.
// Padded q-rows produce NaN (sum=0) but their stores are guarded.
// ---------------------------------------------------------------------------
__global__ __launch_bounds__(128)
void attn_mma_kernel(const bf16* __restrict__ qkv,
                     const bf16* __restrict__ biasmat,
                     bf16* __restrict__ ao) {
    __shared__ __align__(16) bf16 sm[3 * 64 * 32];   // Q,K,V: 64 rows x 64B each

    int blk = blockIdx.x;
    int h = blk % HEADS, w = blk / HEADS;
    int widx = w & 63;
    int wi = widx >> 3, wj = widx & 7;
    int cls = ((wi == 7) ? 2 : 0) + ((wj == 7) ? 1 : 0);
    const bf16* bm = biasmat + (size_t)(h * 4 + cls) * 4096;
    int r0 = w * NWIN;
    int tid = threadIdx.x, lane = tid & 31, wid = tid >> 5;

    uint32_t sb = sptr(sm);

    const uint4 z4 = make_uint4(0, 0, 0, 0);
    for (int e = tid; e < 768; e += 128) {
        int mat = e >> 8;               // 0=Q 1=K 2=V
        int rg  = e & 255;
        int row = rg >> 2, g = rg & 3;
        uint32_t dst = sb + mat * 4096 + row * 64 + ((g ^ ((row >> 1) & 3)) << 4);
        uint4 v = z4;
        if (row < NWIN)
            v = *(const uint4*)(qkv + (size_t)(r0 + row) * 576 + mat * 192
                                + h * HD + g * 8);
        *(uint4*)((char*)sm + (dst - sb)) = v;
    }
    __syncthreads();

    int qbase = wid * 16;
    int rw = lane & 7;

    float sacc[8][4];
#pragma unroll
    for (int n = 0; n < 8; ++n)
#pragma unroll
        for (int l = 0; l < 4; ++l) sacc[n][l] = 0.f;

    int aHalf = lane >> 4;
    int arow = qbase + (lane & 15);
    uint32_t aAddrBase = sb + arow * 64;
    uint32_t aSw = (arow >> 1) & 3;
    int bHalf = (lane >> 3) & 1;

#pragma unroll
    for (int c = 0; c < 2; ++c) {
        uint32_t af[4];
        ldsm4(af, aAddrBase + ((((c << 1) | aHalf) ^ aSw) << 4));
#pragma unroll
        for (int t = 0; t < 4; ++t) {
            int brow = t * 16 + ((lane >> 4) << 3) + rw;
            uint32_t bq[4];
            ldsm4(bq, sb + 4096 + brow * 64
                  + ((((c << 1) | bHalf) ^ ((brow >> 1) & 3)) << 4));
            mma_bf16(sacc[2 * t],     af, bq[0], bq[1]);
            mma_bf16(sacc[2 * t + 1], af, bq[2], bq[3]);
        }
    }

    int rA = qbase + (lane >> 2);
    int rB = rA + 8;
    const bf16* bmA = bm + rA * 64 + ((lane & 3) << 1);
    const bf16* bmB = bm + rB * 64 + ((lane & 3) << 1);

    // softmax without max-subtraction; key block n=7 fully masked
    float sum0 = 0.f, sum1 = 0.f;
#pragma unroll
    for (int n = 0; n < 7; ++n) {
        uint32_t bb0 = *(const uint32_t*)(bmA + n * 8);
        uint32_t bb1 = *(const uint32_t*)(bmB + n * 8);
        sacc[n][0] = __expf(sacc[n][0] * SCALE_Q + bflo(bb0));
        sacc[n][1] = __expf(sacc[n][1] * SCALE_Q + bfhi(bb0));
        sacc[n][2] = __expf(sacc[n][2] * SCALE_Q + bflo(bb1));
        sacc[n][3] = __expf(sacc[n][3] * SCALE_Q + bfhi(bb1));
        sum0 += sacc[n][0] + sacc[n][1];
        sum1 += sacc[n][2] + sacc[n][3];
    }
    sum0 += __shfl_xor_sync(0xffffffffu, sum0, 1);
    sum0 += __shfl_xor_sync(0xffffffffu, sum0, 2);
    sum1 += __shfl_xor_sync(0xffffffffu, sum1, 1);
    sum1 += __shfl_xor_sync(0xffffffffu, sum1, 2);
    float inv0 = 1.f / sum0, inv1 = 1.f / sum1;

    uint32_t pA[8], pB[8];
#pragma unroll
    for (int n = 0; n < 7; ++n) {
        pA[n] = packbf(sacc[n][0] * inv0, sacc[n][1] * inv0);
        pB[n] = packbf(sacc[n][2] * inv1, sacc[n][3] * inv1);
    }
    pA[7] = 0; pB[7] = 0;

    float oacc[4][4];
#pragma unroll
    for (int d = 0; d < 4; ++d)
#pragma unroll
        for (int l = 0; l < 4; ++l) oacc[d][l] = 0.f;

#pragma unroll
    for (int kc = 0; kc < 4; ++kc) {
        uint32_t af[4] = { pA[2 * kc], pB[2 * kc], pA[2 * kc + 1], pB[2 * kc + 1] };
        int vrow = kc * 16 + (((lane >> 3) & 1) << 3) + rw;
        uint32_t vswz = (vrow >> 1) & 3;
        int ghalf = (lane >> 4) & 1;
        uint32_t v01[4], v23[4];
        ldsm4t(v01, sb + 8192 + vrow * 64 + (((0 + ghalf) ^ vswz) << 4));
        ldsm4t(v23, sb + 8192 + vrow * 64 + (((2 + ghalf) ^ vswz) << 4));
        mma_bf16(oacc[0], af, v01[0], v01[1]);
        mma_bf16(oacc[1], af, v01[2], v01[3]);
        mma_bf16(oacc[2], af, v23[0], v23[1]);
        mma_bf16(oacc[3], af, v23[2], v23[3]);
    }

    int colb = h * HD + ((lane & 3) << 1);
    if (rA < NWIN) {
        bf16* op = ao + (size_t)(r0 + rA) * DIM + colb;
#pragma unroll
        for (int d = 0; d < 4; ++d)
            *(uint32_t*)(op + d * 8) = packbf(oacc[d][0], oacc[d][1]);
    }
    if (rB < NWIN) {
        bf16* op = ao + (size_t)(r0 + rB) * DIM + colb;
#pragma unroll
        for (int d = 0; d < 4; ++d)
            *(uint32_t*)(op + d * 8) = packbf(oacc[d][2], oacc[d][3]);
    }
}

// ---------------------------------------------------------------------------
// K1: LayerNorm1 + roll(-3,-3) + window partition -> bf16 win
// ---------------------------------------------------------------------------
__global__ __launch_bounds__(256)
void ln1_win_kernel(const float* __restrict__ x,
                    const float* __restrict__ gam,
                    const float* __restrict__ bet,
                    bf16* __restrict__ win) {
    __shared__ float sm[32][193];
    int p0  = blockIdx.x * 32;
    int b   = p0 / PIX, yx0 = p0 % PIX;
    int tid = threadIdx.x, warp = tid >> 5, lane = tid & 31;

    const float* xb = x + (size_t)b * (DIM * PIX) + yx0;
#pragma unroll
    for (int cc = 0; cc < 24; ++cc) {
        int c = warp + cc * 8;
        sm[lane][c] = xb[(size_t)c * PIX + lane];
    }
    __syncthreads();

#pragma unroll
    for (int t = 0; t < 4; ++t) {
        int pix = warp * 4 + t;
        float v[6], s = 0.f, sq = 0.f;
#pragma unroll
        for (int j = 0; j < 6; ++j) {
            float u = sm[pix][lane + j * 32];
            v[j] = u; s += u; sq += u * u;
        }
#pragma unroll
        for (int o = 16; o; o >>= 1) {
            s  += __shfl_xor_sync(0xffffffffu, s,  o);
            sq += __shfl_xor_sync(0xffffffffu, sq, o);
        }
        float mu   = s * (1.f / DIM);
        float var  = sq * (1.f / DIM) - mu * mu;
        float rstd = rsqrtf(var + 1e-5f);

        int yx = yx0 + pix;
        int y  = yx / HW, xx = yx % HW;
        int y2 = (y  + HW - SHIFTV) % HW;
        int x2 = (xx + HW - SHIFTV) % HW;
        int r  = b * PIX + ((y2 / WS) * NW_GRID + (x2 / WS)) * NWIN
               + (y2 % WS) * WS + (x2 % WS);
        bf16* wp = win + (size_t)r * DIM;
#pragma unroll
        for (int j = 0; j < 6; ++j) {
            int c = lane + j * 32;
            wp[c] = __float2bfloat16((v[j] - mu) * rstd * gam[c] + bet[c]);
        }
    }
}

// ---------------------------------------------------------------------------
// K5: h2 = LN2(x + window-reverse(po)).  x1 is NOT materialized — the
// fc2 epilogue recomputes x + po directly.
// ---------------------------------------------------------------------------
__global__ __launch_bounds__(256)
void addln2_kernel(const float* __restrict__ x,
                   const bf16* __restrict__ po,
                   const float* __restrict__ gam,
                   const float* __restrict__ bet,
                   bf16* __restrict__ h2) {
    __shared__ float sm[32][193];
    int p0  = blockIdx.x * 32;
    int b   = p0 / PIX, yx0 = p0 % PIX;
    int tid = threadIdx.x, warp = tid >> 5, lane = tid & 31;

#pragma unroll
    for (int t = 0; t < 4; ++t) {
        int pix = warp * 4 + t;
        int yx = yx0 + pix;
        int y  = yx / HW, xx = yx % HW;
        int y2 = (y  + HW - SHIFTV) % HW;
        int x2 = (xx + HW - SHIFTV) % HW;
        int r  = b * PIX + ((y2 / WS) * NW_GRID + (x2 / WS)) * NWIN
               + (y2 % WS) * WS + (x2 % WS);
        const bf16* pp = po + (size_t)r * DIM;
#pragma unroll
        for (int j = 0; j < 6; ++j) {
            int c = lane + j * 32;
            sm[pix][c] = __bfloat162float(pp[c]);
        }
    }
    __syncthreads();

    const float* xb = x + (size_t)b * (DIM * PIX) + yx0;
#pragma unroll
    for (int cc = 0; cc < 24; ++cc) {
        int c = warp + cc * 8;
        sm[lane][c] += xb[(size_t)c * PIX + lane];
    }
    __syncthreads();

#pragma unroll
    for (int t = 0; t < 4; ++t) {
        int pix = warp * 4 + t;
        float v[6], s = 0.f, sq = 0.f;
#pragma unroll
        for (int j = 0; j < 6; ++j) {
            float u = sm[pix][lane + j * 32];
            v[j] = u; s += u; sq += u * u;
        }
#pragma unroll
        for (int o = 16; o; o >>= 1) {
            s  += __shfl_xor_sync(0xffffffffu, s,  o);
            sq += __shfl_xor_sync(0xffffffffu, sq, o);
        }
        float mu   = s * (1.f / DIM);
        float var  = sq * (1.f / DIM) - mu * mu;
        float rstd = rsqrtf(var + 1e-5f);

        bf16* hp = h2 + (size_t)(p0 + pix) * DIM;
#pragma unroll
        for (int j = 0; j < 6; ++j) {
            int c = lane + j * 32;
            hp[c] = __float2bfloat16((v[j] - mu) * rstd * gam[c] + bet[c]);
        }
    }
}

// ---------------------------------------------------------------------------
// Launch
// ---------------------------------------------------------------------------
extern "C" void kernel_launch(void* const* d_in, const int* in_sizes, int n_in,
                              void* d_out, int out_size) {
    const float* x      = (const float*)d_in[0];
    const float* n1g    = (const float*)d_in[1];
    const float* n1b    = (const float*)d_in[2];
    const float* qkv_w  = (const float*)d_in[3];
    const float* qkv_b  = (const float*)d_in[4];
    const float* proj_w = (const float*)d_in[5];
    const float* proj_b = (const float*)d_in[6];
    const float* relb   = (const float*)d_in[7];
    const float* n2g    = (const float*)d_in[8];
    const float* n2b    = (const float*)d_in[9];
    const float* fc1_w  = (const float*)d_in[10];
    const float* fc1_b  = (const float*)d_in[11];
    const float* fc2_w  = (const float*)d_in[12];
    const float* fc2_b  = (const float*)d_in[13];
    float* out = (float*)d_out;

    bf16 *ba, *bb, *bg, *bpo, *wqkv, *wproj, *wfc1, *wfc2, *bmat;
    cudaGetSymbolAddress((void**)&ba,   gb_a);
    cudaGetSymbolAddress((void**)&bb,   gb_b);
    cudaGetSymbolAddress((void**)&bg,   gb_big);
    cudaGetSymbolAddress((void**)&bpo,  gb_po);
    cudaGetSymbolAddress((void**)&wqkv, g_qkv_wt);
    cudaGetSymbolAddress((void**)&wproj,g_proj_wt);
    cudaGetSymbolAddress((void**)&wfc1, g_fc1_wt);
    cudaGetSymbolAddress((void**)&wfc2, g_fc2_wt);
    cudaGetSymbolAddress((void**)&bmat, g_biasmat);

    cudaFuncSetAttribute(mma_gemm<2,1>, cudaFuncAttributeMaxDynamicSharedMemorySize, SMEM_BRES1);
    cudaFuncSetAttribute(mma_gemm<1,1>, cudaFuncAttributeMaxDynamicSharedMemorySize, SMEM_BRES1);
    cudaFuncSetAttribute(mma_gemm<3,0>, cudaFuncAttributeMaxDynamicSharedMemorySize, SMEM_BRES0);

    int dev = 0, nsm = 148;
    cudaGetDevice(&dev);
    cudaDeviceGetAttribute(&nsm, cudaDevAttrMultiProcessorCount, dev);
    int grid = nsm * 2;

    // 0) setup: weight transposes + bias/mask matrices, one launch
    setup_all<<<456, dim3(32, 8)>>>(qkv_w, proj_w, fc1_w, fc2_w,
                                    wqkv, wproj, wfc1, wfc2, relb, bmat);

    // 1) LN1 + roll + window partition -> ba = win[50176,192] bf16
    ln1_win_kernel<<<NPIX / 32, 256>>>(x, n1g, n1b, ba);

    // 2) QKV GEMM -> bg[50176,576] bf16
    mma_gemm<2,1><<<grid, 256, SMEM_BRES1>>>(ba, wqkv, qkv_b, bg,
                                             nullptr, nullptr, 576, 192);
    // 3) MMA attention -> bb[50176,192] bf16
    attn_mma_kernel<<<1024 * HEADS, 128>>>(bg, bmat, bb);

    // 4) proj GEMM -> bpo bf16
    mma_gemm<2,1><<<grid, 256, SMEM_BRES1>>>(bb, wproj, proj_b, bpo,
                                             nullptr, nullptr, 192, 192);
    // 5) LN2(x + reverse(po)) -> ba = h2 bf16   (x1 not materialized)
    addln2_kernel<<<NPIX / 32, 256>>>(x, bpo, n2g, n2b, ba);

    // 6) fc1 + GELU -> bg[50176,768] bf16
    mma_gemm<1,1><<<grid, 256, SMEM_BRES1>>>(ba, wfc1, fc1_b, bg,
                                             nullptr, nullptr, 768, 192);
    // 7) fc2 + fused double residual -> out = x + reverse(po) + mlp (NCHW fp32)
    mma_gemm<3,0><<<grid, 256, SMEM_BRES0>>>(bg, wfc2, fc2_b, out,
                                             x, bpo, 192, 768);
}

// round 16
// speedup vs baseline: 1.1553x; 1.0033x over previous
#include <cuda_runtime.h>
#include <cuda_bf16.h>
#include <math.h>
#include <stdint.h>

// ---------------------------------------------------------------------------
// Problem constants
// ---------------------------------------------------------------------------
#define BATCH   16
#define DIM     192
#define HW      56
#define PIX     3136            // 56*56
#define NPIX    50176           // 16*3136
#define WS      7
#define SHIFTV  3
#define NWIN    49
#define HEADS   6
#define HD      32
#define NW_GRID 8
#define SCALE_Q 0.1767766952966369f

typedef __nv_bfloat16 bf16;

// ---------------------------------------------------------------------------
// Scratch buffers (allocation-free: device globals)
// ---------------------------------------------------------------------------
__device__ __align__(128) bf16  gb_a   [NPIX * DIM];   // win (ln1 out) / h2 (ln2 out)
__device__ __align__(128) bf16  gb_b   [NPIX * DIM];   // attn out
__device__ __align__(128) bf16  gb_big [NPIX * 768];   // qkv out (576 used) / fc1 out
__device__ __align__(128) bf16  gb_po  [NPIX * DIM];   // proj out (bf16)
// transposed bf16 weights Wt[N][K]
__device__ __align__(128) bf16 g_qkv_wt [576 * 192];
__device__ __align__(128) bf16 g_proj_wt[192 * 192];
__device__ __align__(128) bf16 g_fc1_wt [768 * 192];
__device__ __align__(128) bf16 g_fc2_wt [192 * 768];
// precomputed attention bias+mask matrices: [head*4+cls][64][64] bf16
__device__ __align__(128) bf16 g_biasmat[24 * 64 * 64];

// ---------------------------------------------------------------------------
// PTX helpers
// ---------------------------------------------------------------------------
__device__ __forceinline__ void mma_bf16(float c[4], const uint32_t a[4],
                                         const uint32_t b0, const uint32_t b1) {
    asm volatile(
        "mma.sync.aligned.m16n8k16.row.col.f32.bf16.bf16.f32 "
        "{%0,%1,%2,%3}, {%4,%5,%6,%7}, {%8,%9}, {%0,%1,%2,%3};"
        : "+f"(c[0]), "+f"(c[1]), "+f"(c[2]), "+f"(c[3])
        : "r"(a[0]), "r"(a[1]), "r"(a[2]), "r"(a[3]),
          "r"(b0), "r"(b1));
}
__device__ __forceinline__ void ldsm4(uint32_t r[4], uint32_t addr) {
    asm volatile("ldmatrix.sync.aligned.m8n8.x4.shared.b16 {%0,%1,%2,%3}, [%4];"
                 : "=r"(r[0]), "=r"(r[1]), "=r"(r[2]), "=r"(r[3]) : "r"(addr));
}
__device__ __forceinline__ void ldsm4t(uint32_t r[4], uint32_t addr) {
    asm volatile("ldmatrix.sync.aligned.m8n8.x4.trans.shared.b16 {%0,%1,%2,%3}, [%4];"
                 : "=r"(r[0]), "=r"(r[1]), "=r"(r[2]), "=r"(r[3]) : "r"(addr));
}
__device__ __forceinline__ void cp16(uint32_t dst, const void* src) {
    asm volatile("cp.async.cg.shared.global [%0], [%1], 16;"
                 :: "r"(dst), "l"(src));
}
__device__ __forceinline__ void cp_commit() {
    asm volatile("cp.async.commit_group;" ::: "memory");
}
template <int N>
__device__ __forceinline__ void cp_wait() {
    asm volatile("cp.async.wait_group %0;" :: "n"(N) : "memory");
}
__device__ __forceinline__ uint32_t sptr(const void* p) {
    return (uint32_t)__cvta_generic_to_shared(p);
}
__device__ __forceinline__ float bflo(uint32_t u) {
    return __uint_as_float(u << 16);
}
__device__ __forceinline__ float bfhi(uint32_t u) {
    return __uint_as_float(u & 0xffff0000u);
}
__device__ __forceinline__ uint32_t packbf(float a, float b) {
    __nv_bfloat162 t = __floats2bfloat162_rn(a, b);
    return *(uint32_t*)&t;
}

// ---------------------------------------------------------------------------
// Persistent bf16 tensor-core GEMM: C[NPIX,Ntot] = A[NPIX,K] @ Wt[N,K]^T + bias
// BM=128, BN=96, BKC=32; 8 warps (4M x 2N), warp tile 32x48; 2 CTAs/SM.
// PAIR pipeline: one cp.async group covers TWO k-stages -> syncs halved.
// BRES=1 (K=192): full B tile resident in smem (6 panels); pairs stage A only.
// BRES=0 (fc2):   A and B staged per pair (2-pair rings).
// MODE: 1 = bf16+GELU out, 2 = bf16 out,
//       3 = fp32 NCHW out, fused double residual out = x + rev(po) + acc+bias
// ---------------------------------------------------------------------------
#define BM 128
#define BN 96
#define BKC 32
#define MT (NPIX / BM)          // 392 m-tiles
#define ASTG (BM * 64)          // 8192 per A stage
#define BPNL (BN * 64)          // 6144 per B panel
#define SMEM_BRES1 (4 * ASTG + 6 * BPNL)   // 69632
#define SMEM_BRES0 (4 * ASTG + 4 * BPNL)   // 57344

template <int MODE, int BRES>
__global__ __launch_bounds__(256, 2)
void mma_gemm(const bf16* __restrict__ A, const bf16* __restrict__ Bt,
              const float* __restrict__ bias, void* __restrict__ Cout,
              const float* __restrict__ xaux, const bf16* __restrict__ poaux,
              int Ntot, int K) {
    extern __shared__ char dsm[];
    const uint32_t aAbase = sptr(dsm);
    const uint32_t aBbase = aAbase + 4 * ASTG;

    int tid = threadIdx.x, lane = tid & 31, wid = tid >> 5;
    int wm = wid & 3, wn = wid >> 2;

    const int S = K / BKC;          // 6 or 24 (even)
    int NT = Ntot / BN;
    int ntiles = MT * NT;
    int base = ntiles / gridDim.x, rem = ntiles % gridDim.x;
    int bidx = blockIdx.x;
    int t0 = bidx * base + (bidx < rem ? bidx : rem);
    int t1 = t0 + base + (bidx < rem ? 1 : 0);
    if (t0 >= t1) return;

    // ldmatrix per-lane address components (validated pattern)
    uint32_t aRow[2], aSw[2];
    int aHalf = lane >> 4;
#pragma unroll
    for (int tm = 0; tm < 2; ++tm) {
        int r = wm * 32 + tm * 16 + (lane & 15);
        aRow[tm] = r * 64;
        aSw[tm]  = (r >> 1) & 3;
    }
    uint32_t bRow[3], bSw[3];
    int bHalf = (lane >> 3) & 1;
#pragma unroll
    for (int p = 0; p < 3; ++p) {
        int r = wn * 48 + p * 16 + ((lane >> 4) << 3) + (lane & 7);
        bRow[p] = r * 64;
        bSw[p]  = (r >> 1) & 3;
    }

    float acc[2][6][4];
#pragma unroll
    for (int i = 0; i < 2; ++i)
#pragma unroll
        for (int j = 0; j < 6; ++j)
#pragma unroll
            for (int l = 0; l < 4; ++l) acc[i][j][l] = 0.f;

    auto compute = [&](uint32_t bA, uint32_t bB) {
#pragma unroll
        for (int kss = 0; kss < 2; ++kss) {
            uint32_t af[2][4], bq[3][4];
#pragma unroll
            for (int tm = 0; tm < 2; ++tm)
                ldsm4(af[tm], bA + aRow[tm]
                      + ((((kss << 1) | aHalf) ^ aSw[tm]) << 4));
#pragma unroll
            for (int p = 0; p < 3; ++p)
                ldsm4(bq[p], bB + bRow[p]
                      + ((((kss << 1) | bHalf) ^ bSw[p]) << 4));
#pragma unroll
            for (int tm = 0; tm < 2; ++tm)
#pragma unroll
                for (int tn = 0; tn < 6; ++tn)
                    mma_bf16(acc[tm][tn], af[tm],
                             bq[tn >> 1][(tn & 1) << 1],
                             bq[tn >> 1][((tn & 1) << 1) + 1]);
        }
    };

    auto epi = [&](int m0, int n0) {
        int q = lane & 3;
#pragma unroll
        for (int tm = 0; tm < 2; ++tm) {
            int r = m0 + wm * 32 + tm * 16 + (lane >> 2);
            size_t base1 = 0, base2 = 0;
            int wr1 = 0, wr2 = 0;
            if (MODE == 3) {
                int r2 = r + 8;
                int b1 = r / PIX, yx1 = r % PIX;
                int b2 = r2 / PIX, yx2 = r2 % PIX;
                base1 = (size_t)b1 * (DIM * PIX) + yx1;
                base2 = (size_t)b2 * (DIM * PIX) + yx2;
                int y1 = yx1 / HW, xp1 = yx1 % HW;
                int yy1 = (y1 + HW - SHIFTV) % HW, xx1 = (xp1 + HW - SHIFTV) % HW;
                wr1 = b1 * PIX + ((yy1 / WS) * NW_GRID + xx1 / WS) * NWIN
                    + (yy1 % WS) * WS + (xx1 % WS);
                int y2 = yx2 / HW, xp2 = yx2 % HW;
                int yy2 = (y2 + HW - SHIFTV) % HW, xx2 = (xp2 + HW - SHIFTV) % HW;
                wr2 = b2 * PIX + ((yy2 / WS) * NW_GRID + xx2 / WS) * NWIN
                    + (yy2 % WS) * WS + (xx2 % WS);
            }
#pragma unroll
            for (int tn = 0; tn < 6; ++tn) {
                int cl = wn * 48 + tn * 8 + (q << 1);
                float b0 = __ldg(bias + n0 + cl);
                float b1v = __ldg(bias + n0 + cl + 1);
                float v0 = acc[tm][tn][0] + b0;
                float v1 = acc[tm][tn][1] + b1v;
                float v2 = acc[tm][tn][2] + b0;
                float v3 = acc[tm][tn][3] + b1v;
                if (MODE == 1) {
                    v0 = 0.5f * v0 * (1.f + erff(v0 * 0.70710678118654752f));
                    v1 = 0.5f * v1 * (1.f + erff(v1 * 0.70710678118654752f));
                    v2 = 0.5f * v2 * (1.f + erff(v2 * 0.70710678118654752f));
                    v3 = 0.5f * v3 * (1.f + erff(v3 * 0.70710678118654752f));
                }
                if (MODE == 3) {
                    uint32_t pw1 = *(const uint32_t*)(poaux + (size_t)wr1 * DIM + n0 + cl);
                    uint32_t pw2 = *(const uint32_t*)(poaux + (size_t)wr2 * DIM + n0 + cl);
                    float* O = (float*)Cout;
                    size_t o00 = base1 + (size_t)(n0 + cl) * PIX;
                    size_t o01 = base1 + (size_t)(n0 + cl + 1) * PIX;
                    size_t o10 = base2 + (size_t)(n0 + cl) * PIX;
                    size_t o11 = base2 + (size_t)(n0 + cl + 1) * PIX;
                    O[o00] = xaux[o00] + bflo(pw1) + v0;
                    O[o01] = xaux[o01] + bfhi(pw1) + v1;
                    O[o10] = xaux[o10] + bflo(pw2) + v2;
                    O[o11] = xaux[o11] + bfhi(pw2) + v3;
                } else {
                    bf16* C = (bf16*)Cout;
                    *(__nv_bfloat162*)(C + (size_t)r * Ntot + n0 + cl) =
                        __floats2bfloat162_rn(v0, v1);
                    *(__nv_bfloat162*)(C + (size_t)(r + 8) * Ntot + n0 + cl) =
                        __floats2bfloat162_rn(v2, v3);
                }
            }
        }
#pragma unroll
        for (int i = 0; i < 2; ++i)
#pragma unroll
            for (int j = 0; j < 6; ++j)
#pragma unroll
                for (int l = 0; l < 4; ++l) acc[i][j][l] = 0.f;
    };

    if (BRES) {
        // ---- B resident; pairs stage A only ----
        int t = t0;
        while (t < t1) {
            int nIdx = t / MT;
            int tend = (nIdx + 1) * MT; if (tend > t1) tend = t1;
            int n0 = nIdx * BN;
            __syncthreads();               // drain previous group's smem use
            {   // load all S B panels (one group)
                int total = S * 384;
                for (int e = tid; e < total; e += 256) {
                    int panel = e / 384;
                    int rg = e - panel * 384;
                    int r = rg >> 2, g4 = rg & 3;
                    uint32_t dst = aBbase + panel * BPNL + r * 64
                                 + ((g4 ^ ((r >> 1) & 3)) << 4);
                    cp16(dst, Bt + (size_t)(n0 + r) * K + panel * BKC + g4 * 8);
                }
                cp_commit();
            }
            int GP = (tend - t) * (S >> 1);
            int sm0 = (t % MT) * BM, sks = 0, spb = 0;
            auto stagePair = [&]() {
#pragma unroll
                for (int hf = 0; hf < 2; ++hf) {
                    uint32_t dstb = aAbase + (spb * 2 + hf) * ASTG;
                    int kc = (sks + hf) * BKC;
#pragma unroll
                    for (int i = 0; i < 2; ++i) {
                        int e = (i << 8) + tid;
                        int row = e >> 2, g4 = e & 3;
                        cp16(dstb + row * 64 + ((g4 ^ ((row >> 1) & 3)) << 4),
                             A + (size_t)(sm0 + row) * K + kc + g4 * 8);
                    }
                }
                cp_commit();
                sks += 2; if (sks == S) { sks = 0; sm0 += BM; }
                spb ^= 1;
            };
            stagePair();                   // prologue: pair 0 in flight
            int cm0 = (t % MT) * BM, cks = 0, cpb = 0;
            for (int g = 0; g < GP; ++g) {
                cp_wait<0>();
                __syncthreads();
                if (g + 1 < GP) stagePair();
                compute(aAbase + (cpb * 2) * ASTG, aBbase + cks * BPNL);
                ++cks;
                compute(aAbase + (cpb * 2 + 1) * ASTG, aBbase + cks * BPNL);
                if (++cks == S) { cks = 0; epi(cm0, n0); cm0 += BM; }
                cpb ^= 1;
            }
            t = tend;
        }
    } else {
        // ---- streaming A+B pairs (fc2) ----
        int GP = (t1 - t0) * (S >> 1);
        int sm0 = (t0 % MT) * BM, sn0 = (t0 / MT) * BN, sks = 0, spb = 0;
        auto stagePair = [&]() {
#pragma unroll
            for (int hf = 0; hf < 2; ++hf) {
                uint32_t dA = aAbase + (spb * 2 + hf) * ASTG;
                uint32_t dB = aBbase + (spb * 2 + hf) * BPNL;
                int kc = (sks + hf) * BKC;
#pragma unroll
                for (int i = 0; i < 2; ++i) {
                    int e = (i << 8) + tid;
                    int row = e >> 2, g4 = e & 3;
                    cp16(dA + row * 64 + ((g4 ^ ((row >> 1) & 3)) << 4),
                         A + (size_t)(sm0 + row) * K + kc + g4 * 8);
                }
                {
                    int row = tid >> 2, g4 = tid & 3;
                    cp16(dB + row * 64 + ((g4 ^ ((row >> 1) & 3)) << 4),
                         Bt + (size_t)(sn0 + row) * K + kc + g4 * 8);
                }
                if (tid < 128) {
                    int e = 256 + tid;
                    int row = e >> 2, g4 = e & 3;
                    cp16(dB + row * 64 + ((g4 ^ ((row >> 1) & 3)) << 4),
                         Bt + (size_t)(sn0 + row) * K + kc + g4 * 8);
                }
            }
            cp_commit();
            sks += 2;
            if (sks == S) {
                sks = 0; sm0 += BM;
                if (sm0 == NPIX) { sm0 = 0; sn0 += BN; }
            }
            spb ^= 1;
        };
        stagePair();
        int cm0 = (t0 % MT) * BM, cn0 = (t0 / MT) * BN, cks = 0, cpb = 0;
        for (int g = 0; g < GP; ++g) {
            cp_wait<0>();
            __syncthreads();
            if (g + 1 < GP) stagePair();
            compute(aAbase + (cpb * 2) * ASTG, aBbase + (cpb * 2) * BPNL);
            ++cks;
            compute(aAbase + (cpb * 2 + 1) * ASTG, aBbase + (cpb * 2 + 1) * BPNL);
            if (++cks == S) {
                cks = 0; epi(cm0, cn0); cm0 += BM;
                if (cm0 == NPIX) { cm0 = 0; cn0 += BN; }
            }
            cpb ^= 1;
        }
    }
}

// ---------------------------------------------------------------------------
// Setup: 4 weight transposes (+bf16) AND bias/mask matrices in ONE launch.
// ---------------------------------------------------------------------------
__global__ void setup_all(const float* __restrict__ w0, const float* __restrict__ w1,
                          const float* __restrict__ w2, const float* __restrict__ w3,
                          bf16* __restrict__ t0, bf16* __restrict__ t1,
                          bf16* __restrict__ t2, bf16* __restrict__ t3,
                          const float* __restrict__ rel_bias,
                          bf16* __restrict__ bm) {
    int bid = blockIdx.x;
    int ftid = threadIdx.y * 32 + threadIdx.x;
    if (bid >= 432) {
        int mat = bid - 432;             // 0..23
        int h = mat >> 2, cls = mat & 3;
        for (int e = ftid; e < 4096; e += 256) {
            int qq = e >> 6, kk = e & 63;
            float v = -1e9f;
            if (qq < NWIN && kk < NWIN) {
                int qi = qq / WS, qj = qq % WS, ki = kk / WS, kj = kk % WS;
                int ryq = (cls & 2) ? ((qi < WS - SHIFTV) ? 1 : 2) : 0;
                int rxq = (cls & 1) ? ((qj < WS - SHIFTV) ? 1 : 2) : 0;
                int ryk = (cls & 2) ? ((ki < WS - SHIFTV) ? 1 : 2) : 0;
                int rxk = (cls & 1) ? ((kj < WS - SHIFTV) ? 1 : 2) : 0;
                if (ryq == ryk && rxq == rxk)
                    v = rel_bias[((qi - ki + 6) * 13 + (qj - kj + 6)) * HEADS + h];
            }
            bm[mat * 4096 + e] = __float2bfloat16(v);
        }
        return;
    }
    __shared__ float t[32][33];
    const float* W; bf16* Wt; int K, N, tn, tk;
    if (bid < 108)      { W = w0; Wt = t0; K = 192; N = 576; tn = bid % 18; tk = bid / 18; }
    else if (bid < 144) { bid -= 108; W = w1; Wt = t1; K = 192; N = 192; tn = bid % 6;  tk = bid / 6; }
    else if (bid < 288) { bid -= 144; W = w2; Wt = t2; K = 192; N = 768; tn = bid % 24; tk = bid / 24; }
    else                { bid -= 288; W = w3; Wt = t3; K = 768; N = 192; tn = bid % 6;  tk = bid / 6; }
    int k0 = tk * 32, n0 = tn * 32;
    int tx = threadIdx.x, ty = threadIdx.y;
#pragma unroll
    for (int i = 0; i < 32; i += 8)
        t[ty + i][tx] = W[(size_t)(k0 + ty + i) * N + n0 + tx];
    __syncthreads();
#pragma unroll
    for (int i = 0; i < 32; i += 8)
        Wt[(size_t)(n0 + ty + i) * K + k0 + tx] = __float2bfloat16(t[tx][ty + i]);
}

// ---------------------------------------------------------------------------
// K3: MMA windowed attention (unchanged — passing)
// ---------------------------------------------------------------------------
__global__ __launch_bounds__(128)
void attn_mma_kernel(const bf16* __restrict__ qkv,
                     const bf16* __restrict__ biasmat,
                     bf16* __restrict__ ao) {
    __shared__ __align__(16) bf16 sm[3 * 64 * 32];   // Q,K,V: 64 rows x 64B each

    int blk = blockIdx.x;
    int h = blk % HEADS, w = blk / HEADS;
    int widx = w & 63;
    int wi = widx >> 3, wj = widx & 7;
    int cls = ((wi == 7) ? 2 : 0) + ((wj == 7) ? 1 : 0);
    const bf16* bm = biasmat + (size_t)(h * 4 + cls) * 4096;
    int r0 = w * NWIN;
    int tid = threadIdx.x, lane = tid & 31, wid = tid >> 5;

    uint32_t sb = sptr(sm);

    const uint4 z4 = make_uint4(0, 0, 0, 0);
    for (int e = tid; e < 768; e += 128) {
        int mat = e >> 8;               // 0=Q 1=K 2=V
        int rg  = e & 255;
        int row = rg >> 2, g = rg & 3;
        uint32_t dst = sb + mat * 4096 + row * 64 + ((g ^ ((row >> 1) & 3)) << 4);
        uint4 v = z4;
        if (row < NWIN)
            v = *(const uint4*)(qkv + (size_t)(r0 + row) * 576 + mat * 192
                                + h * HD + g * 8);
        *(uint4*)((char*)sm + (dst - sb)) = v;
    }
    __syncthreads();

    int qbase = wid * 16;
    int rw = lane & 7;

    float sacc[8][4];
#pragma unroll
    for (int n = 0; n < 8; ++n)
#pragma unroll
        for (int l = 0; l < 4; ++l) sacc[n][l] = 0.f;

    int aHalf = lane >> 4;
    int arow = qbase + (lane & 15);
    uint32_t aAddrBase = sb + arow * 64;
    uint32_t aSw = (arow >> 1) & 3;
    int bHalf = (lane >> 3) & 1;

#pragma unroll
    for (int c = 0; c < 2; ++c) {
        uint32_t af[4];
        ldsm4(af, aAddrBase + ((((c << 1) | aHalf) ^ aSw) << 4));
#pragma unroll
        for (int t = 0; t < 4; ++t) {
            int brow = t * 16 + ((lane >> 4) << 3) + rw;
            uint32_t bq[4];
            ldsm4(bq, sb + 4096 + brow * 64
                  + ((((c << 1) | bHalf) ^ ((brow >> 1) & 3)) << 4));
            mma_bf16(sacc[2 * t],     af, bq[0], bq[1]);
            mma_bf16(sacc[2 * t + 1], af, bq[2], bq[3]);
        }
    }

    int rA = qbase + (lane >> 2);
    int rB = rA + 8;
    const bf16* bmA = bm + rA * 64 + ((lane & 3) << 1);
    const bf16* bmB = bm + rB * 64 + ((lane & 3) << 1);

    float sum0 = 0.f, sum1 = 0.f;
#pragma unroll
    for (int n = 0; n < 7; ++n) {
        uint32_t bb0 = *(const uint32_t*)(bmA + n * 8);
        uint32_t bb1 = *(const uint32_t*)(bmB + n * 8);
        sacc[n][0] = __expf(sacc[n][0] * SCALE_Q + bflo(bb0));
        sacc[n][1] = __expf(sacc[n][1] * SCALE_Q + bfhi(bb0));
        sacc[n][2] = __expf(sacc[n][2] * SCALE_Q + bflo(bb1));
        sacc[n][3] = __expf(sacc[n][3] * SCALE_Q + bfhi(bb1));
        sum0 += sacc[n][0] + sacc[n][1];
        sum1 += sacc[n][2] + sacc[n][3];
    }
    sum0 += __shfl_xor_sync(0xffffffffu, sum0, 1);
    sum0 += __shfl_xor_sync(0xffffffffu, sum0, 2);
    sum1 += __shfl_xor_sync(0xffffffffu, sum1, 1);
    sum1 += __shfl_xor_sync(0xffffffffu, sum1, 2);
    float inv0 = 1.f / sum0, inv1 = 1.f / sum1;

    uint32_t pA[8], pB[8];
#pragma unroll
    for (int n = 0; n < 7; ++n) {
        pA[n] = packbf(sacc[n][0] * inv0, sacc[n][1] * inv0);
        pB[n] = packbf(sacc[n][2] * inv1, sacc[n][3] * inv1);
    }
    pA[7] = 0; pB[7] = 0;

    float oacc[4][4];
#pragma unroll
    for (int d = 0; d < 4; ++d)
#pragma unroll
        for (int l = 0; l < 4; ++l) oacc[d][l] = 0.f;

#pragma unroll
    for (int kc = 0; kc < 4; ++kc) {
        uint32_t af[4] = { pA[2 * kc], pB[2 * kc], pA[2 * kc + 1], pB[2 * kc + 1] };
        int vrow = kc * 16 + (((lane >> 3) & 1) << 3) + rw;
        uint32_t vswz = (vrow >> 1) & 3;
        int ghalf = (lane >> 4) & 1;
        uint32_t v01[4], v23[4];
        ldsm4t(v01, sb + 8192 + vrow * 64 + (((0 + ghalf) ^ vswz) << 4));
        ldsm4t(v23, sb + 8192 + vrow * 64 + (((2 + ghalf) ^ vswz) << 4));
        mma_bf16(oacc[0], af, v01[0], v01[1]);
        mma_bf16(oacc[1], af, v01[2], v01[3]);
        mma_bf16(oacc[2], af, v23[0], v23[1]);
        mma_bf16(oacc[3], af, v23[2], v23[3]);
    }

    int colb = h * HD + ((lane & 3) << 1);
    if (rA < NWIN) {
        bf16* op = ao + (size_t)(r0 + rA) * DIM + colb;
#pragma unroll
        for (int d = 0; d < 4; ++d)
            *(uint32_t*)(op + d * 8) = packbf(oacc[d][0], oacc[d][1]);
    }
    if (rB < NWIN) {
        bf16* op = ao + (size_t)(r0 + rB) * DIM + colb;
#pragma unroll
        for (int d = 0; d < 4; ++d)
            *(uint32_t*)(op + d * 8) = packbf(oacc[d][2], oacc[d][3]);
    }
}

// ---------------------------------------------------------------------------
// K1: LayerNorm1 + roll + window partition. 64-pixel tiles.
// Global accesses vectorized (float2 / bf162); smem accesses SCALAR
// (row stride 193 floats is odd -> float2 on smem rows would misalign).
// ---------------------------------------------------------------------------
#define LNS 193
#define LN_SMEM (64 * LNS * 4)

__global__ __launch_bounds__(256, 2)
void ln1_win_kernel(const float* __restrict__ x,
                    const float* __restrict__ gam,
                    const float* __restrict__ bet,
                    bf16* __restrict__ win) {
    extern __shared__ float sm[];
    int p0  = blockIdx.x * 64;
    int b   = p0 / PIX, yx0 = p0 % PIX;
    int tid = threadIdx.x, warp = tid >> 5, lane = tid & 31;

    const float* xb = x + (size_t)b * (DIM * PIX) + yx0;
#pragma unroll
    for (int cc = 0; cc < 24; ++cc) {
        int c = warp + cc * 8;
        float2 v = *(const float2*)(xb + (size_t)c * PIX + 2 * lane);
        sm[(2 * lane) * LNS + c]     = v.x;
        sm[(2 * lane + 1) * LNS + c] = v.y;
    }
    __syncthreads();

#pragma unroll
    for (int t = 0; t < 8; ++t) {
        int pix = warp * 8 + t;
        const float* row = sm + pix * LNS;
        float s = 0.f, sq = 0.f;
#pragma unroll
        for (int j = 0; j < 3; ++j) {
            int c = 2 * lane + j * 64;
            float u0 = row[c], u1 = row[c + 1];
            s  += u0 + u1;
            sq += u0 * u0 + u1 * u1;
        }
#pragma unroll
        for (int o = 16; o; o >>= 1) {
            s  += __shfl_xor_sync(0xffffffffu, s,  o);
            sq += __shfl_xor_sync(0xffffffffu, sq, o);
        }
        float mu   = s * (1.f / DIM);
        float var  = sq * (1.f / DIM) - mu * mu;
        float rstd = rsqrtf(var + 1e-5f);

        int yx = yx0 + pix;
        int y  = yx / HW, xx = yx % HW;
        int y2 = (y  + HW - SHIFTV) % HW;
        int x2 = (xx + HW - SHIFTV) % HW;
        int r  = b * PIX + ((y2 / WS) * NW_GRID + (x2 / WS)) * NWIN
               + (y2 % WS) * WS + (x2 % WS);
        bf16* wp = win + (size_t)r * DIM;
#pragma unroll
        for (int j = 0; j < 3; ++j) {
            int c = 2 * lane + j * 64;
            float u0 = row[c], u1 = row[c + 1];
            float a0 = (u0 - mu) * rstd * gam[c] + bet[c];
            float a1 = (u1 - mu) * rstd * gam[c + 1] + bet[c + 1];
            *(uint32_t*)(wp + c) = packbf(a0, a1);
        }
    }
}

// ---------------------------------------------------------------------------
// K5: h2 = LN2(x + window-reverse(po)). 64-pixel tiles; same alignment rules.
// ---------------------------------------------------------------------------
__global__ __launch_bounds__(256, 2)
void addln2_kernel(const float* __restrict__ x,
                   const bf16* __restrict__ po,
                   const float* __restrict__ gam,
                   const float* __restrict__ bet,
                   bf16* __restrict__ h2) {
    extern __shared__ float sm[];
    int p0  = blockIdx.x * 64;
    int b   = p0 / PIX, yx0 = p0 % PIX;
    int tid = threadIdx.x, warp = tid >> 5, lane = tid & 31;

    // Phase 1: gather proj-out rows (row-major bf162 global, scalar smem)
#pragma unroll
    for (int t = 0; t < 8; ++t) {
        int pix = warp * 8 + t;
        int yx = yx0 + pix;
        int y  = yx / HW, xx = yx % HW;
        int y2 = (y  + HW - SHIFTV) % HW;
        int x2 = (xx + HW - SHIFTV) % HW;
        int r  = b * PIX + ((y2 / WS) * NW_GRID + (x2 / WS)) * NWIN
               + (y2 % WS) * WS + (x2 % WS);
        const bf16* pp = po + (size_t)r * DIM;
        float* row = sm + pix * LNS;
#pragma unroll
        for (int j = 0; j < 3; ++j) {
            int c = 2 * lane + j * 64;
            uint32_t u = *(const uint32_t*)(pp + c);
            row[c]     = bflo(u);
            row[c + 1] = bfhi(u);
        }
    }
    __syncthreads();

    // Phase 2: add NCHW x (float2 global, scalar smem)
    const float* xb = x + (size_t)b * (DIM * PIX) + yx0;
#pragma unroll
    for (int cc = 0; cc < 24; ++cc) {
        int c = warp + cc * 8;
        float2 v = *(const float2*)(xb + (size_t)c * PIX + 2 * lane);
        sm[(2 * lane) * LNS + c]     += v.x;
        sm[(2 * lane + 1) * LNS + c] += v.y;
    }
    __syncthreads();

    // Phase 3: LN per pixel (scalar smem reads, bf162 global writes)
#pragma unroll
    for (int t = 0; t < 8; ++t) {
        int pix = warp * 8 + t;
        const float* row = sm + pix * LNS;
        float s = 0.f, sq = 0.f;
#pragma unroll
        for (int j = 0; j < 3; ++j) {
            int c = 2 * lane + j * 64;
            float u0 = row[c], u1 = row[c + 1];
            s  += u0 + u1;
            sq += u0 * u0 + u1 * u1;
        }
#pragma unroll
        for (int o = 16; o; o >>= 1) {
            s  += __shfl_xor_sync(0xffffffffu, s,  o);
            sq += __shfl_xor_sync(0xffffffffu, sq, o);
        }
        float mu   = s * (1.f / DIM);
        float var  = sq * (1.f / DIM) - mu * mu;
        float rstd = rsqrtf(var + 1e-5f);

        bf16* hp = h2 + (size_t)(p0 + pix) * DIM;
#pragma unroll
        for (int j = 0; j < 3; ++j) {
            int c = 2 * lane + j * 64;
            float u0 = row[c], u1 = row[c + 1];
            float a0 = (u0 - mu) * rstd * gam[c] + bet[c];
            float a1 = (u1 - mu) * rstd * gam[c + 1] + bet[c + 1];
            *(uint32_t*)(hp + c) = packbf(a0, a1);
        }
    }
}

// ---------------------------------------------------------------------------
// Launch
// ---------------------------------------------------------------------------
extern "C" void kernel_launch(void* const* d_in, const int* in_sizes, int n_in,
                              void* d_out, int out_size) {
    const float* x      = (const float*)d_in[0];
    const float* n1g    = (const float*)d_in[1];
    const float* n1b    = (const float*)d_in[2];
    const float* qkv_w  = (const float*)d_in[3];
    const float* qkv_b  = (const float*)d_in[4];
    const float* proj_w = (const float*)d_in[5];
    const float* proj_b = (const float*)d_in[6];
    const float* relb   = (const float*)d_in[7];
    const float* n2g    = (const float*)d_in[8];
    const float* n2b    = (const float*)d_in[9];
    const float* fc1_w  = (const float*)d_in[10];
    const float* fc1_b  = (const float*)d_in[11];
    const float* fc2_w  = (const float*)d_in[12];
    const float* fc2_b  = (const float*)d_in[13];
    float* out = (float*)d_out;

    bf16 *ba, *bb, *bg, *bpo, *wqkv, *wproj, *wfc1, *wfc2, *bmat;
    cudaGetSymbolAddress((void**)&ba,   gb_a);
    cudaGetSymbolAddress((void**)&bb,   gb_b);
    cudaGetSymbolAddress((void**)&bg,   gb_big);
    cudaGetSymbolAddress((void**)&bpo,  gb_po);
    cudaGetSymbolAddress((void**)&wqkv, g_qkv_wt);
    cudaGetSymbolAddress((void**)&wproj,g_proj_wt);
    cudaGetSymbolAddress((void**)&wfc1, g_fc1_wt);
    cudaGetSymbolAddress((void**)&wfc2, g_fc2_wt);
    cudaGetSymbolAddress((void**)&bmat, g_biasmat);

    cudaFuncSetAttribute(mma_gemm<2,1>, cudaFuncAttributeMaxDynamicSharedMemorySize, SMEM_BRES1);
    cudaFuncSetAttribute(mma_gemm<1,1>, cudaFuncAttributeMaxDynamicSharedMemorySize, SMEM_BRES1);
    cudaFuncSetAttribute(mma_gemm<3,0>, cudaFuncAttributeMaxDynamicSharedMemorySize, SMEM_BRES0);
    cudaFuncSetAttribute(ln1_win_kernel, cudaFuncAttributeMaxDynamicSharedMemorySize, LN_SMEM);
    cudaFuncSetAttribute(addln2_kernel,  cudaFuncAttributeMaxDynamicSharedMemorySize, LN_SMEM);

    int dev = 0, nsm = 148;
    cudaGetDevice(&dev);
    cudaDeviceGetAttribute(&nsm, cudaDevAttrMultiProcessorCount, dev);
    int grid = nsm * 2;

    // 0) setup: weight transposes + bias/mask matrices, one launch
    setup_all<<<456, dim3(32, 8)>>>(qkv_w, proj_w, fc1_w, fc2_w,
                                    wqkv, wproj, wfc1, wfc2, relb, bmat);

    // 1) LN1 + roll + window partition -> ba = win[50176,192] bf16
    ln1_win_kernel<<<NPIX / 64, 256, LN_SMEM>>>(x, n1g, n1b, ba);

    // 2) QKV GEMM -> bg[50176,576] bf16
    mma_gemm<2,1><<<grid, 256, SMEM_BRES1>>>(ba, wqkv, qkv_b, bg,
                                             nullptr, nullptr, 576, 192);
    // 3) MMA attention -> bb[50176,192] bf16
    attn_mma_kernel<<<1024 * HEADS, 128>>>(bg, bmat, bb);

    // 4) proj GEMM -> bpo bf16
    mma_gemm<2,1><<<grid, 256, SMEM_BRES1>>>(bb, wproj, proj_b, bpo,
                                             nullptr, nullptr, 192, 192);
    // 5) LN2(x + reverse(po)) -> ba = h2 bf16
    addln2_kernel<<<NPIX / 64, 256, LN_SMEM>>>(x, bpo, n2g, n2b, ba);

    // 6) fc1 + GELU -> bg[50176,768] bf16
    mma_gemm<1,1><<<grid, 256, SMEM_BRES1>>>(ba, wfc1, fc1_b, bg,
                                             nullptr, nullptr, 768, 192);
    // 7) fc2 + fused double residual -> out = x + reverse(po) + mlp (NCHW fp32)
    mma_gemm<3,0><<<grid, 256, SMEM_BRES0>>>(bg, wfc2, fc2_b, out,
                                             x, bpo, 192, 768);
}

// round 17
// speedup vs baseline: 1.2053x; 1.0434x over previous
#include <cuda_runtime.h>
#include <cuda_bf16.h>
#include <math.h>
#include <stdint.h>

// ---------------------------------------------------------------------------
// Problem constants
// ---------------------------------------------------------------------------
#define BATCH   16
#define DIM     192
#define HW      56
#define PIX     3136            // 56*56
#define NPIX    50176           // 16*3136
#define WS      7
#define SHIFTV  3
#define NWIN    49
#define HEADS   6
#define HD      32
#define NW_GRID 8
#define SCALE_Q 0.1767766952966369f

typedef __nv_bfloat16 bf16;

// ---------------------------------------------------------------------------
// Scratch buffers (allocation-free: device globals)
// ---------------------------------------------------------------------------
__device__ __align__(128) bf16  gb_a   [NPIX * DIM];   // win (ln1 out) / h2 (ln2 out)
__device__ __align__(128) bf16  gb_b   [NPIX * DIM];   // attn out
__device__ __align__(128) bf16  gb_big [NPIX * 768];   // qkv out (576 used) / fc1 out
__device__ __align__(128) bf16  gb_po  [NPIX * DIM];   // proj out (bf16)
// transposed bf16 weights Wt[N][K]
__device__ __align__(128) bf16 g_qkv_wt [576 * 192];
__device__ __align__(128) bf16 g_proj_wt[192 * 192];
__device__ __align__(128) bf16 g_fc1_wt [768 * 192];
__device__ __align__(128) bf16 g_fc2_wt [192 * 768];
// precomputed attention bias+mask matrices: [head*4+cls][64][64] bf16
__device__ __align__(128) bf16 g_biasmat[24 * 64 * 64];

// ---------------------------------------------------------------------------
// PTX helpers
// ---------------------------------------------------------------------------
__device__ __forceinline__ void mma_bf16(float c[4], const uint32_t a[4],
                                         const uint32_t b0, const uint32_t b1) {
    asm volatile(
        "mma.sync.aligned.m16n8k16.row.col.f32.bf16.bf16.f32 "
        "{%0,%1,%2,%3}, {%4,%5,%6,%7}, {%8,%9}, {%0,%1,%2,%3};"
        : "+f"(c[0]), "+f"(c[1]), "+f"(c[2]), "+f"(c[3])
        : "r"(a[0]), "r"(a[1]), "r"(a[2]), "r"(a[3]),
          "r"(b0), "r"(b1));
}
__device__ __forceinline__ void ldsm4(uint32_t r[4], uint32_t addr) {
    asm volatile("ldmatrix.sync.aligned.m8n8.x4.shared.b16 {%0,%1,%2,%3}, [%4];"
                 : "=r"(r[0]), "=r"(r[1]), "=r"(r[2]), "=r"(r[3]) : "r"(addr));
}
__device__ __forceinline__ void ldsm4t(uint32_t r[4], uint32_t addr) {
    asm volatile("ldmatrix.sync.aligned.m8n8.x4.trans.shared.b16 {%0,%1,%2,%3}, [%4];"
                 : "=r"(r[0]), "=r"(r[1]), "=r"(r[2]), "=r"(r[3]) : "r"(addr));
}
__device__ __forceinline__ void cp16(uint32_t dst, const void* src) {
    asm volatile("cp.async.cg.shared.global [%0], [%1], 16;"
                 :: "r"(dst), "l"(src));
}
__device__ __forceinline__ void cp_commit() {
    asm volatile("cp.async.commit_group;" ::: "memory");
}
template <int N>
__device__ __forceinline__ void cp_wait() {
    asm volatile("cp.async.wait_group %0;" :: "n"(N) : "memory");
}
__device__ __forceinline__ uint32_t sptr(const void* p) {
    return (uint32_t)__cvta_generic_to_shared(p);
}
__device__ __forceinline__ float bflo(uint32_t u) {
    return __uint_as_float(u << 16);
}
__device__ __forceinline__ float bfhi(uint32_t u) {
    return __uint_as_float(u & 0xffff0000u);
}
__device__ __forceinline__ uint32_t packbf(float a, float b) {
    __nv_bfloat162 t = __floats2bfloat162_rn(a, b);
    return *(uint32_t*)&t;
}
// tanh-form GELU via sigmoid: v * sigmoid(1.5957691*(v + 0.044715 v^3))
__device__ __forceinline__ float gelu_fast(float v) {
    float z = 1.5957691216057308f * (v + 0.044715f * v * v * v);
    return __fdividef(v, 1.f + __expf(-z));
}

// ---------------------------------------------------------------------------
// Persistent bf16 tensor-core GEMM: C[NPIX,Ntot] = A[NPIX,K] @ Wt[N,K]^T + bias
// BM=128, BN=96, BKC=32; 8 warps (4M x 2N), warp tile 32x48; 2 CTAs/SM.
// PAIR pipeline: one cp.async group covers TWO k-stages.
// BRES=1 (K=192): full B tile resident in smem (6 panels); pairs stage A only.
// BRES=0 (fc2):   A and B staged per pair (2-pair rings).
// MODE: 1 = bf16+GELU out, 2 = bf16 out,
//       3 = fp32 NCHW out, fused double residual out = x + rev(po) + acc+bias
// ---------------------------------------------------------------------------
#define BM 128
#define BN 96
#define BKC 32
#define MT (NPIX / BM)          // 392 m-tiles
#define ASTG (BM * 64)          // 8192 per A stage
#define BPNL (BN * 64)          // 6144 per B panel
#define SMEM_BRES1 (4 * ASTG + 6 * BPNL)   // 69632
#define SMEM_BRES0 (4 * ASTG + 4 * BPNL)   // 57344

template <int MODE, int BRES>
__global__ __launch_bounds__(256, 2)
void mma_gemm(const bf16* __restrict__ A, const bf16* __restrict__ Bt,
              const float* __restrict__ bias, void* __restrict__ Cout,
              const float* __restrict__ xaux, const bf16* __restrict__ poaux,
              int Ntot, int K) {
    extern __shared__ char dsm[];
    const uint32_t aAbase = sptr(dsm);
    const uint32_t aBbase = aAbase + 4 * ASTG;

    int tid = threadIdx.x, lane = tid & 31, wid = tid >> 5;
    int wm = wid & 3, wn = wid >> 2;

    const int S = K / BKC;          // 6 or 24 (even)
    int NT = Ntot / BN;
    int ntiles = MT * NT;
    int base = ntiles / gridDim.x, rem = ntiles % gridDim.x;
    int bidx = blockIdx.x;
    int t0 = bidx * base + (bidx < rem ? bidx : rem);
    int t1 = t0 + base + (bidx < rem ? 1 : 0);
    if (t0 >= t1) return;

    uint32_t aRow[2], aSw[2];
    int aHalf = lane >> 4;
#pragma unroll
    for (int tm = 0; tm < 2; ++tm) {
        int r = wm * 32 + tm * 16 + (lane & 15);
        aRow[tm] = r * 64;
        aSw[tm]  = (r >> 1) & 3;
    }
    uint32_t bRow[3], bSw[3];
    int bHalf = (lane >> 3) & 1;
#pragma unroll
    for (int p = 0; p < 3; ++p) {
        int r = wn * 48 + p * 16 + ((lane >> 4) << 3) + (lane & 7);
        bRow[p] = r * 64;
        bSw[p]  = (r >> 1) & 3;
    }

    float acc[2][6][4];
#pragma unroll
    for (int i = 0; i < 2; ++i)
#pragma unroll
        for (int j = 0; j < 6; ++j)
#pragma unroll
            for (int l = 0; l < 4; ++l) acc[i][j][l] = 0.f;

    auto compute = [&](uint32_t bA, uint32_t bB) {
#pragma unroll
        for (int kss = 0; kss < 2; ++kss) {
            uint32_t af[2][4], bq[3][4];
#pragma unroll
            for (int tm = 0; tm < 2; ++tm)
                ldsm4(af[tm], bA + aRow[tm]
                      + ((((kss << 1) | aHalf) ^ aSw[tm]) << 4));
#pragma unroll
            for (int p = 0; p < 3; ++p)
                ldsm4(bq[p], bB + bRow[p]
                      + ((((kss << 1) | bHalf) ^ bSw[p]) << 4));
#pragma unroll
            for (int tm = 0; tm < 2; ++tm)
#pragma unroll
                for (int tn = 0; tn < 6; ++tn)
                    mma_bf16(acc[tm][tn], af[tm],
                             bq[tn >> 1][(tn & 1) << 1],
                             bq[tn >> 1][((tn & 1) << 1) + 1]);
        }
    };

    auto epi = [&](int m0, int n0) {
        int q = lane & 3;
#pragma unroll
        for (int tm = 0; tm < 2; ++tm) {
            int r = m0 + wm * 32 + tm * 16 + (lane >> 2);
            size_t base1 = 0, base2 = 0;
            int wr1 = 0, wr2 = 0;
            if (MODE == 3) {
                int r2 = r + 8;
                int b1 = r / PIX, yx1 = r % PIX;
                int b2 = r2 / PIX, yx2 = r2 % PIX;
                base1 = (size_t)b1 * (DIM * PIX) + yx1;
                base2 = (size_t)b2 * (DIM * PIX) + yx2;
                int y1 = yx1 / HW, xp1 = yx1 % HW;
                int yy1 = (y1 + HW - SHIFTV) % HW, xx1 = (xp1 + HW - SHIFTV) % HW;
                wr1 = b1 * PIX + ((yy1 / WS) * NW_GRID + xx1 / WS) * NWIN
                    + (yy1 % WS) * WS + (xx1 % WS);
                int y2 = yx2 / HW, xp2 = yx2 % HW;
                int yy2 = (y2 + HW - SHIFTV) % HW, xx2 = (xp2 + HW - SHIFTV) % HW;
                wr2 = b2 * PIX + ((yy2 / WS) * NW_GRID + xx2 / WS) * NWIN
                    + (yy2 % WS) * WS + (xx2 % WS);
            }
#pragma unroll
            for (int tn = 0; tn < 6; ++tn) {
                int cl = wn * 48 + tn * 8 + (q << 1);
                float b0 = __ldg(bias + n0 + cl);
                float b1v = __ldg(bias + n0 + cl + 1);
                float v0 = acc[tm][tn][0] + b0;
                float v1 = acc[tm][tn][1] + b1v;
                float v2 = acc[tm][tn][2] + b0;
                float v3 = acc[tm][tn][3] + b1v;
                if (MODE == 1) {
                    v0 = gelu_fast(v0);
                    v1 = gelu_fast(v1);
                    v2 = gelu_fast(v2);
                    v3 = gelu_fast(v3);
                }
                if (MODE == 3) {
                    uint32_t pw1 = *(const uint32_t*)(poaux + (size_t)wr1 * DIM + n0 + cl);
                    uint32_t pw2 = *(const uint32_t*)(poaux + (size_t)wr2 * DIM + n0 + cl);
                    float* O = (float*)Cout;
                    size_t o00 = base1 + (size_t)(n0 + cl) * PIX;
                    size_t o01 = base1 + (size_t)(n0 + cl + 1) * PIX;
                    size_t o10 = base2 + (size_t)(n0 + cl) * PIX;
                    size_t o11 = base2 + (size_t)(n0 + cl + 1) * PIX;
                    O[o00] = xaux[o00] + bflo(pw1) + v0;
                    O[o01] = xaux[o01] + bfhi(pw1) + v1;
                    O[o10] = xaux[o10] + bflo(pw2) + v2;
                    O[o11] = xaux[o11] + bfhi(pw2) + v3;
                } else {
                    bf16* C = (bf16*)Cout;
                    *(__nv_bfloat162*)(C + (size_t)r * Ntot + n0 + cl) =
                        __floats2bfloat162_rn(v0, v1);
                    *(__nv_bfloat162*)(C + (size_t)(r + 8) * Ntot + n0 + cl) =
                        __floats2bfloat162_rn(v2, v3);
                }
            }
        }
#pragma unroll
        for (int i = 0; i < 2; ++i)
#pragma unroll
            for (int j = 0; j < 6; ++j)
#pragma unroll
                for (int l = 0; l < 4; ++l) acc[i][j][l] = 0.f;
    };

    if (BRES) {
        int t = t0;
        while (t < t1) {
            int nIdx = t / MT;
            int tend = (nIdx + 1) * MT; if (tend > t1) tend = t1;
            int n0 = nIdx * BN;
            __syncthreads();
            {
                int total = S * 384;
                for (int e = tid; e < total; e += 256) {
                    int panel = e / 384;
                    int rg = e - panel * 384;
                    int r = rg >> 2, g4 = rg & 3;
                    uint32_t dst = aBbase + panel * BPNL + r * 64
                                 + ((g4 ^ ((r >> 1) & 3)) << 4);
                    cp16(dst, Bt + (size_t)(n0 + r) * K + panel * BKC + g4 * 8);
                }
                cp_commit();
            }
            int GP = (tend - t) * (S >> 1);
            int sm0 = (t % MT) * BM, sks = 0, spb = 0;
            auto stagePair = [&]() {
#pragma unroll
                for (int hf = 0; hf < 2; ++hf) {
                    uint32_t dstb = aAbase + (spb * 2 + hf) * ASTG;
                    int kc = (sks + hf) * BKC;
#pragma unroll
                    for (int i = 0; i < 2; ++i) {
                        int e = (i << 8) + tid;
                        int row = e >> 2, g4 = e & 3;
                        cp16(dstb + row * 64 + ((g4 ^ ((row >> 1) & 3)) << 4),
                             A + (size_t)(sm0 + row) * K + kc + g4 * 8);
                    }
                }
                cp_commit();
                sks += 2; if (sks == S) { sks = 0; sm0 += BM; }
                spb ^= 1;
            };
            stagePair();
            int cm0 = (t % MT) * BM, cks = 0, cpb = 0;
            for (int g = 0; g < GP; ++g) {
                cp_wait<0>();
                __syncthreads();
                if (g + 1 < GP) stagePair();
                compute(aAbase + (cpb * 2) * ASTG, aBbase + cks * BPNL);
                ++cks;
                compute(aAbase + (cpb * 2 + 1) * ASTG, aBbase + cks * BPNL);
                if (++cks == S) { cks = 0; epi(cm0, n0); cm0 += BM; }
                cpb ^= 1;
            }
            t = tend;
        }
    } else {
        int GP = (t1 - t0) * (S >> 1);
        int sm0 = (t0 % MT) * BM, sn0 = (t0 / MT) * BN, sks = 0, spb = 0;
        auto stagePair = [&]() {
#pragma unroll
            for (int hf = 0; hf < 2; ++hf) {
                uint32_t dA = aAbase + (spb * 2 + hf) * ASTG;
                uint32_t dB = aBbase + (spb * 2 + hf) * BPNL;
                int kc = (sks + hf) * BKC;
#pragma unroll
                for (int i = 0; i < 2; ++i) {
                    int e = (i << 8) + tid;
                    int row = e >> 2, g4 = e & 3;
                    cp16(dA + row * 64 + ((g4 ^ ((row >> 1) & 3)) << 4),
                         A + (size_t)(sm0 + row) * K + kc + g4 * 8);
                }
                {
                    int row = tid >> 2, g4 = tid & 3;
                    cp16(dB + row * 64 + ((g4 ^ ((row >> 1) & 3)) << 4),
                         Bt + (size_t)(sn0 + row) * K + kc + g4 * 8);
                }
                if (tid < 128) {
                    int e = 256 + tid;
                    int row = e >> 2, g4 = e & 3;
                    cp16(dB + row * 64 + ((g4 ^ ((row >> 1) & 3)) << 4),
                         Bt + (size_t)(sn0 + row) * K + kc + g4 * 8);
                }
            }
            cp_commit();
            sks += 2;
            if (sks == S) {
                sks = 0; sm0 += BM;
                if (sm0 == NPIX) { sm0 = 0; sn0 += BN; }
            }
            spb ^= 1;
        };
        stagePair();
        int cm0 = (t0 % MT) * BM, cn0 = (t0 / MT) * BN, cks = 0, cpb = 0;
        for (int g = 0; g < GP; ++g) {
            cp_wait<0>();
            __syncthreads();
            if (g + 1 < GP) stagePair();
            compute(aAbase + (cpb * 2) * ASTG, aBbase + (cpb * 2) * BPNL);
            ++cks;
            compute(aAbase + (cpb * 2 + 1) * ASTG, aBbase + (cpb * 2 + 1) * BPNL);
            if (++cks == S) {
                cks = 0; epi(cm0, cn0); cm0 += BM;
                if (cm0 == NPIX) { cm0 = 0; cn0 += BN; }
            }
            cpb ^= 1;
        }
    }
}

// ---------------------------------------------------------------------------
// K3: MMA windowed attention (unchanged — passing)
// ---------------------------------------------------------------------------
__global__ __launch_bounds__(128)
void attn_mma_kernel(const bf16* __restrict__ qkv,
                     const bf16* __restrict__ biasmat,
                     bf16* __restrict__ ao) {
    __shared__ __align__(16) bf16 sm[3 * 64 * 32];

    int blk = blockIdx.x;
    int h = blk % HEADS, w = blk / HEADS;
    int widx = w & 63;
    int wi = widx >> 3, wj = widx & 7;
    int cls = ((wi == 7) ? 2 : 0) + ((wj == 7) ? 1 : 0);
    const bf16* bm = biasmat + (size_t)(h * 4 + cls) * 4096;
    int r0 = w * NWIN;
    int tid = threadIdx.x, lane = tid & 31, wid = tid >> 5;

    uint32_t sb = sptr(sm);

    const uint4 z4 = make_uint4(0, 0, 0, 0);
    for (int e = tid; e < 768; e += 128) {
        int mat = e >> 8;
        int rg  = e & 255;
        int row = rg >> 2, g = rg & 3;
        uint32_t dst = sb + mat * 4096 + row * 64 + ((g ^ ((row >> 1) & 3)) << 4);
        uint4 v = z4;
        if (row < NWIN)
            v = *(const uint4*)(qkv + (size_t)(r0 + row) * 576 + mat * 192
                                + h * HD + g * 8);
        *(uint4*)((char*)sm + (dst - sb)) = v;
    }
    __syncthreads();

    int qbase = wid * 16;
    int rw = lane & 7;

    float sacc[8][4];
#pragma unroll
    for (int n = 0; n < 8; ++n)
#pragma unroll
        for (int l = 0; l < 4; ++l) sacc[n][l] = 0.f;

    int aHalf = lane >> 4;
    int arow = qbase + (lane & 15);
    uint32_t aAddrBase = sb + arow * 64;
    uint32_t aSw = (arow >> 1) & 3;
    int bHalf = (lane >> 3) & 1;

#pragma unroll
    for (int c = 0; c < 2; ++c) {
        uint32_t af[4];
        ldsm4(af, aAddrBase + ((((c << 1) | aHalf) ^ aSw) << 4));
#pragma unroll
        for (int t = 0; t < 4; ++t) {
            int brow = t * 16 + ((lane >> 4) << 3) + rw;
            uint32_t bq[4];
            ldsm4(bq, sb + 4096 + brow * 64
                  + ((((c << 1) | bHalf) ^ ((brow >> 1) & 3)) << 4));
            mma_bf16(sacc[2 * t],     af, bq[0], bq[1]);
            mma_bf16(sacc[2 * t + 1], af, bq[2], bq[3]);
        }
    }

    int rA = qbase + (lane >> 2);
    int rB = rA + 8;
    const bf16* bmA = bm + rA * 64 + ((lane & 3) << 1);
    const bf16* bmB = bm + rB * 64 + ((lane & 3) << 1);

    float sum0 = 0.f, sum1 = 0.f;
#pragma unroll
    for (int n = 0; n < 7; ++n) {
        uint32_t bb0 = *(const uint32_t*)(bmA + n * 8);
        uint32_t bb1 = *(const uint32_t*)(bmB + n * 8);
        sacc[n][0] = __expf(sacc[n][0] * SCALE_Q + bflo(bb0));
        sacc[n][1] = __expf(sacc[n][1] * SCALE_Q + bfhi(bb0));
        sacc[n][2] = __expf(sacc[n][2] * SCALE_Q + bflo(bb1));
        sacc[n][3] = __expf(sacc[n][3] * SCALE_Q + bfhi(bb1));
        sum0 += sacc[n][0] + sacc[n][1];
        sum1 += sacc[n][2] + sacc[n][3];
    }
    sum0 += __shfl_xor_sync(0xffffffffu, sum0, 1);
    sum0 += __shfl_xor_sync(0xffffffffu, sum0, 2);
    sum1 += __shfl_xor_sync(0xffffffffu, sum1, 1);
    sum1 += __shfl_xor_sync(0xffffffffu, sum1, 2);
    float inv0 = 1.f / sum0, inv1 = 1.f / sum1;

    uint32_t pA[8], pB[8];
#pragma unroll
    for (int n = 0; n < 7; ++n) {
        pA[n] = packbf(sacc[n][0] * inv0, sacc[n][1] * inv0);
        pB[n] = packbf(sacc[n][2] * inv1, sacc[n][3] * inv1);
    }
    pA[7] = 0; pB[7] = 0;

    float oacc[4][4];
#pragma unroll
    for (int d = 0; d < 4; ++d)
#pragma unroll
        for (int l = 0; l < 4; ++l) oacc[d][l] = 0.f;

#pragma unroll
    for (int kc = 0; kc < 4; ++kc) {
        uint32_t af[4] = { pA[2 * kc], pB[2 * kc], pA[2 * kc + 1], pB[2 * kc + 1] };
        int vrow = kc * 16 + (((lane >> 3) & 1) << 3) + rw;
        uint32_t vswz = (vrow >> 1) & 3;
        int ghalf = (lane >> 4) & 1;
        uint32_t v01[4], v23[4];
        ldsm4t(v01, sb + 8192 + vrow * 64 + (((0 + ghalf) ^ vswz) << 4));
        ldsm4t(v23, sb + 8192 + vrow * 64 + (((2 + ghalf) ^ vswz) << 4));
        mma_bf16(oacc[0], af, v01[0], v01[1]);
        mma_bf16(oacc[1], af, v01[2], v01[3]);
        mma_bf16(oacc[2], af, v23[0], v23[1]);
        mma_bf16(oacc[3], af, v23[2], v23[3]);
    }

    int colb = h * HD + ((lane & 3) << 1);
    if (rA < NWIN) {
        bf16* op = ao + (size_t)(r0 + rA) * DIM + colb;
#pragma unroll
        for (int d = 0; d < 4; ++d)
            *(uint32_t*)(op + d * 8) = packbf(oacc[d][0], oacc[d][1]);
    }
    if (rB < NWIN) {
        bf16* op = ao + (size_t)(r0 + rB) * DIM + colb;
#pragma unroll
        for (int d = 0; d < 4; ++d)
            *(uint32_t*)(op + d * 8) = packbf(oacc[d][2], oacc[d][3]);
    }
}

// ---------------------------------------------------------------------------
// K1 (fused): blocks 0..783 = LN1 + roll + window partition (64-pixel tiles);
// blocks 784..1215 = weight transposes; blocks 1216..1239 = bias matrices.
// LN blocks use dynamic smem (64x193 f); setup uses static smem.
// ---------------------------------------------------------------------------
#define LNS 193
#define LN_SMEM (64 * LNS * 4)
#define LN_BLOCKS (NPIX / 64)            // 784

__global__ __launch_bounds__(256, 2)
void ln1_setup_kernel(const float* __restrict__ x,
                      const float* __restrict__ gam,
                      const float* __restrict__ bet,
                      bf16* __restrict__ win,
                      const float* __restrict__ w0, const float* __restrict__ w1,
                      const float* __restrict__ w2, const float* __restrict__ w3,
                      bf16* __restrict__ t0, bf16* __restrict__ t1,
                      bf16* __restrict__ t2, bf16* __restrict__ t3,
                      const float* __restrict__ rel_bias,
                      bf16* __restrict__ bmout) {
    extern __shared__ float sm[];
    int bidg = blockIdx.x;
    int tid = threadIdx.x, warp = tid >> 5, lane = tid & 31;

    if (bidg >= LN_BLOCKS) {
        int bid = bidg - LN_BLOCKS;
        if (bid >= 432) {
            int mat = bid - 432;             // 0..23
            int h = mat >> 2, cls = mat & 3;
            for (int e = tid; e < 4096; e += 256) {
                int qq = e >> 6, kk = e & 63;
                float v = -1e9f;
                if (qq < NWIN && kk < NWIN) {
                    int qi = qq / WS, qj = qq % WS, ki = kk / WS, kj = kk % WS;
                    int ryq = (cls & 2) ? ((qi < WS - SHIFTV) ? 1 : 2) : 0;
                    int rxq = (cls & 1) ? ((qj < WS - SHIFTV) ? 1 : 2) : 0;
                    int ryk = (cls & 2) ? ((ki < WS - SHIFTV) ? 1 : 2) : 0;
                    int rxk = (cls & 1) ? ((kj < WS - SHIFTV) ? 1 : 2) : 0;
                    if (ryq == ryk && rxq == rxk)
                        v = rel_bias[((qi - ki + 6) * 13 + (qj - kj + 6)) * HEADS + h];
                }
                bmout[mat * 4096 + e] = __float2bfloat16(v);
            }
            return;
        }
        // transpose path (use dynamic smem as 32x33 tile)
        float* t = sm;
        const float* W; bf16* Wt; int K, N, tn, tk;
        if (bid < 108)      { W = w0; Wt = t0; K = 192; N = 576; tn = bid % 18; tk = bid / 18; }
        else if (bid < 144) { bid -= 108; W = w1; Wt = t1; K = 192; N = 192; tn = bid % 6;  tk = bid / 6; }
        else if (bid < 288) { bid -= 144; W = w2; Wt = t2; K = 192; N = 768; tn = bid % 24; tk = bid / 24; }
        else                { bid -= 288; W = w3; Wt = t3; K = 768; N = 192; tn = bid % 6;  tk = bid / 6; }
        int k0 = tk * 32, n0 = tn * 32;
        int tx = lane, ty = warp;          // 32 x 8
#pragma unroll
        for (int i = 0; i < 32; i += 8)
            t[(ty + i) * 33 + tx] = W[(size_t)(k0 + ty + i) * N + n0 + tx];
        __syncthreads();
#pragma unroll
        for (int i = 0; i < 32; i += 8)
            Wt[(size_t)(n0 + ty + i) * K + k0 + tx] = __float2bfloat16(t[tx * 33 + ty + i]);
        return;
    }

    // ---- LN1 path ----
    int p0  = bidg * 64;
    int b   = p0 / PIX, yx0 = p0 % PIX;

    const float* xb = x + (size_t)b * (DIM * PIX) + yx0;
#pragma unroll
    for (int cc = 0; cc < 24; ++cc) {
        int c = warp + cc * 8;
        float2 v = *(const float2*)(xb + (size_t)c * PIX + 2 * lane);
        sm[(2 * lane) * LNS + c]     = v.x;
        sm[(2 * lane + 1) * LNS + c] = v.y;
    }
    __syncthreads();

#pragma unroll
    for (int t = 0; t < 8; ++t) {
        int pix = warp * 8 + t;
        const float* row = sm + pix * LNS;
        float s = 0.f, sq = 0.f;
#pragma unroll
        for (int j = 0; j < 3; ++j) {
            int c = 2 * lane + j * 64;
            float u0 = row[c], u1 = row[c + 1];
            s  += u0 + u1;
            sq += u0 * u0 + u1 * u1;
        }
#pragma unroll
        for (int o = 16; o; o >>= 1) {
            s  += __shfl_xor_sync(0xffffffffu, s,  o);
            sq += __shfl_xor_sync(0xffffffffu, sq, o);
        }
        float mu   = s * (1.f / DIM);
        float var  = sq * (1.f / DIM) - mu * mu;
        float rstd = rsqrtf(var + 1e-5f);

        int yx = yx0 + pix;
        int y  = yx / HW, xx = yx % HW;
        int y2 = (y  + HW - SHIFTV) % HW;
        int x2 = (xx + HW - SHIFTV) % HW;
        int r  = b * PIX + ((y2 / WS) * NW_GRID + (x2 / WS)) * NWIN
               + (y2 % WS) * WS + (x2 % WS);
        bf16* wp = win + (size_t)r * DIM;
#pragma unroll
        for (int j = 0; j < 3; ++j) {
            int c = 2 * lane + j * 64;
            float u0 = row[c], u1 = row[c + 1];
            float a0 = (u0 - mu) * rstd * gam[c] + bet[c];
            float a1 = (u1 - mu) * rstd * gam[c + 1] + bet[c + 1];
            *(uint32_t*)(wp + c) = packbf(a0, a1);
        }
    }
}

// ---------------------------------------------------------------------------
// K5: h2 = LN2(x + window-reverse(po)). 64-pixel tiles (unchanged — passing).
// ---------------------------------------------------------------------------
__global__ __launch_bounds__(256, 2)
void addln2_kernel(const float* __restrict__ x,
                   const bf16* __restrict__ po,
                   const float* __restrict__ gam,
                   const float* __restrict__ bet,
                   bf16* __restrict__ h2) {
    extern __shared__ float sm[];
    int p0  = blockIdx.x * 64;
    int b   = p0 / PIX, yx0 = p0 % PIX;
    int tid = threadIdx.x, warp = tid >> 5, lane = tid & 31;

#pragma unroll
    for (int t = 0; t < 8; ++t) {
        int pix = warp * 8 + t;
        int yx = yx0 + pix;
        int y  = yx / HW, xx = yx % HW;
        int y2 = (y  + HW - SHIFTV) % HW;
        int x2 = (xx + HW - SHIFTV) % HW;
        int r  = b * PIX + ((y2 / WS) * NW_GRID + (x2 / WS)) * NWIN
               + (y2 % WS) * WS + (x2 % WS);
        const bf16* pp = po + (size_t)r * DIM;
        float* row = sm + pix * LNS;
#pragma unroll
        for (int j = 0; j < 3; ++j) {
            int c = 2 * lane + j * 64;
            uint32_t u = *(const uint32_t*)(pp + c);
            row[c]     = bflo(u);
            row[c + 1] = bfhi(u);
        }
    }
    __syncthreads();

    const float* xb = x + (size_t)b * (DIM * PIX) + yx0;
#pragma unroll
    for (int cc = 0; cc < 24; ++cc) {
        int c = warp + cc * 8;
        float2 v = *(const float2*)(xb + (size_t)c * PIX + 2 * lane);
        sm[(2 * lane) * LNS + c]     += v.x;
        sm[(2 * lane + 1) * LNS + c] += v.y;
    }
    __syncthreads();

#pragma unroll
    for (int t = 0; t < 8; ++t) {
        int pix = warp * 8 + t;
        const float* row = sm + pix * LNS;
        float s = 0.f, sq = 0.f;
#pragma unroll
        for (int j = 0; j < 3; ++j) {
            int c = 2 * lane + j * 64;
            float u0 = row[c], u1 = row[c + 1];
            s  += u0 + u1;
            sq += u0 * u0 + u1 * u1;
        }
#pragma unroll
        for (int o = 16; o; o >>= 1) {
            s  += __shfl_xor_sync(0xffffffffu, s,  o);
            sq += __shfl_xor_sync(0xffffffffu, sq, o);
        }
        float mu   = s * (1.f / DIM);
        float var  = sq * (1.f / DIM) - mu * mu;
        float rstd = rsqrtf(var + 1e-5f);

        bf16* hp = h2 + (size_t)(p0 + pix) * DIM;
#pragma unroll
        for (int j = 0; j < 3; ++j) {
            int c = 2 * lane + j * 64;
            float u0 = row[c], u1 = row[c + 1];
            float a0 = (u0 - mu) * rstd * gam[c] + bet[c];
            float a1 = (u1 - mu) * rstd * gam[c + 1] + bet[c + 1];
            *(uint32_t*)(hp + c) = packbf(a0, a1);
        }
    }
}

// ---------------------------------------------------------------------------
// Launch
// ---------------------------------------------------------------------------
extern "C" void kernel_launch(void* const* d_in, const int* in_sizes, int n_in,
                              void* d_out, int out_size) {
    const float* x      = (const float*)d_in[0];
    const float* n1g    = (const float*)d_in[1];
    const float* n1b    = (const float*)d_in[2];
    const float* qkv_w  = (const float*)d_in[3];
    const float* qkv_b  = (const float*)d_in[4];
    const float* proj_w = (const float*)d_in[5];
    const float* proj_b = (const float*)d_in[6];
    const float* relb   = (const float*)d_in[7];
    const float* n2g    = (const float*)d_in[8];
    const float* n2b    = (const float*)d_in[9];
    const float* fc1_w  = (const float*)d_in[10];
    const float* fc1_b  = (const float*)d_in[11];
    const float* fc2_w  = (const float*)d_in[12];
    const float* fc2_b  = (const float*)d_in[13];
    float* out = (float*)d_out;

    bf16 *ba, *bb, *bg, *bpo, *wqkv, *wproj, *wfc1, *wfc2, *bmat;
    cudaGetSymbolAddress((void**)&ba,   gb_a);
    cudaGetSymbolAddress((void**)&bb,   gb_b);
    cudaGetSymbolAddress((void**)&bg,   gb_big);
    cudaGetSymbolAddress((void**)&bpo,  gb_po);
    cudaGetSymbolAddress((void**)&wqkv, g_qkv_wt);
    cudaGetSymbolAddress((void**)&wproj,g_proj_wt);
    cudaGetSymbolAddress((void**)&wfc1, g_fc1_wt);
    cudaGetSymbolAddress((void**)&wfc2, g_fc2_wt);
    cudaGetSymbolAddress((void**)&bmat, g_biasmat);

    cudaFuncSetAttribute(mma_gemm<2,1>, cudaFuncAttributeMaxDynamicSharedMemorySize, SMEM_BRES1);
    cudaFuncSetAttribute(mma_gemm<1,1>, cudaFuncAttributeMaxDynamicSharedMemorySize, SMEM_BRES1);
    cudaFuncSetAttribute(mma_gemm<3,0>, cudaFuncAttributeMaxDynamicSharedMemorySize, SMEM_BRES0);
    cudaFuncSetAttribute(ln1_setup_kernel, cudaFuncAttributeMaxDynamicSharedMemorySize, LN_SMEM);
    cudaFuncSetAttribute(addln2_kernel,  cudaFuncAttributeMaxDynamicSharedMemorySize, LN_SMEM);

    int dev = 0, nsm = 148;
    cudaGetDevice(&dev);
    cudaDeviceGetAttribute(&nsm, cudaDevAttrMultiProcessorCount, dev);
    int grid = nsm * 2;

    // 1) fused: LN1+roll+window  AND  weight transposes + bias matrices
    ln1_setup_kernel<<<LN_BLOCKS + 456, 256, LN_SMEM>>>(
        x, n1g, n1b, ba,
        qkv_w, proj_w, fc1_w, fc2_w, wqkv, wproj, wfc1, wfc2, relb, bmat);

    // 2) QKV GEMM -> bg[50176,576] bf16
    mma_gemm<2,1><<<grid, 256, SMEM_BRES1>>>(ba, wqkv, qkv_b, bg,
                                             nullptr, nullptr, 576, 192);
    // 3) MMA attention -> bb[50176,192] bf16
    attn_mma_kernel<<<1024 * HEADS, 128>>>(bg, bmat, bb);

    // 4) proj GEMM -> bpo bf16
    mma_gemm<2,1><<<grid, 256, SMEM_BRES1>>>(bb, wproj, proj_b, bpo,
                                             nullptr, nullptr, 192, 192);
    // 5) LN2(x + reverse(po)) -> ba = h2 bf16
    addln2_kernel<<<NPIX / 64, 256, LN_SMEM>>>(x, bpo, n2g, n2b, ba);

    // 6) fc1 + fast GELU -> bg[50176,768] bf16
    mma_gemm<1,1><<<grid, 256, SMEM_BRES1>>>(ba, wfc1, fc1_b, bg,
                                             nullptr, nullptr, 768, 192);
    // 7) fc2 + fused double residual -> out = x + reverse(po) + mlp (NCHW fp32)
    mma_gemm<3,0><<<grid, 256, SMEM_BRES0>>>(bg, wfc2, fc2_b, out,
                                             x, bpo, 192, 768);
}